// round 9
// baseline (speedup 1.0000x reference)
#include <cuda_runtime.h>
#include <cuda_bf16.h>
#include <cuda_fp16.h>
#include <math.h>
#include <stdint.h>

// ---------------- problem constants ----------------
#define T_TOK   2048
#define D_MODEL 4096
#define N_HEADS 32
#define KV_HEADS 8
#define HEAD_DIM 128
#define QKV_OUT 6144
#define CLIP_V  8.0f
#define GK      4096

// ---------------- scratch (device globals; no allocations) ----------------
__device__ float g_qkv[(size_t)T_TOK * QKV_OUT];

__device__ __nv_bfloat16 g_hid_h[(size_t)T_TOK * D_MODEL];
__device__ __nv_bfloat16 g_hid_l[(size_t)T_TOK * D_MODEL];
__device__ __nv_bfloat16 g_wqkv_h[(size_t)QKV_OUT * D_MODEL];
__device__ __nv_bfloat16 g_wqkv_l[(size_t)QKV_OUT * D_MODEL];
__device__ __nv_bfloat16 g_wo_h[(size_t)D_MODEL * D_MODEL];
__device__ __nv_bfloat16 g_wo_l[(size_t)D_MODEL * D_MODEL];
__device__ __nv_bfloat16 g_att_h[(size_t)T_TOK * D_MODEL];
__device__ __nv_bfloat16 g_att_l[(size_t)T_TOK * D_MODEL];

__device__ __half g_q16[(size_t)T_TOK * D_MODEL];
__device__ __half g_k16[(size_t)T_TOK * KV_HEADS * HEAD_DIM];
__device__ __half g_v16[(size_t)T_TOK * KV_HEADS * HEAD_DIM];

// ---------------- helpers ----------------
__device__ __forceinline__ uint32_t smem_u32(const void* p) {
    uint32_t a;
    asm("{ .reg .u64 t; cvta.to.shared.u64 t, %1; cvt.u32.u64 %0, t; }"
        : "=r"(a) : "l"(p));
    return a;
}
__device__ __forceinline__ void ldsm4(uint32_t addr, uint32_t* r) {
    asm volatile("ldmatrix.sync.aligned.m8n8.x4.shared.b16 {%0,%1,%2,%3}, [%4];"
                 : "=r"(r[0]), "=r"(r[1]), "=r"(r[2]), "=r"(r[3]) : "r"(addr));
}
__device__ __forceinline__ void ldsm4t(uint32_t addr, uint32_t* r) {
    asm volatile("ldmatrix.sync.aligned.m8n8.x4.trans.shared.b16 {%0,%1,%2,%3}, [%4];"
                 : "=r"(r[0]), "=r"(r[1]), "=r"(r[2]), "=r"(r[3]) : "r"(addr));
}
__device__ __forceinline__ void mma_bf16(float* d, const uint32_t* a,
                                         uint32_t b0, uint32_t b1) {
    asm volatile(
        "mma.sync.aligned.m16n8k16.row.col.f32.bf16.bf16.f32 "
        "{%0,%1,%2,%3}, {%4,%5,%6,%7}, {%8,%9}, {%0,%1,%2,%3};"
        : "+f"(d[0]), "+f"(d[1]), "+f"(d[2]), "+f"(d[3])
        : "r"(a[0]), "r"(a[1]), "r"(a[2]), "r"(a[3]), "r"(b0), "r"(b1));
}
__device__ __forceinline__ void mma_fp16(float* d, const uint32_t* a,
                                         uint32_t b0, uint32_t b1) {
    asm volatile(
        "mma.sync.aligned.m16n8k16.row.col.f32.f16.f16.f32 "
        "{%0,%1,%2,%3}, {%4,%5,%6,%7}, {%8,%9}, {%0,%1,%2,%3};"
        : "+f"(d[0]), "+f"(d[1]), "+f"(d[2]), "+f"(d[3])
        : "r"(a[0]), "r"(a[1]), "r"(a[2]), "r"(a[3]), "r"(b0), "r"(b1));
}
__device__ __forceinline__ uint32_t pack_half2(float lo, float hi) {
    uint32_t u;
    asm("cvt.rn.f16x2.f32 %0, %1, %2;" : "=r"(u) : "f"(hi), "f"(lo));
    return u;
}

// ===================================================================
// Split fp32 -> (hi, lo) bf16
// ===================================================================
__global__ __launch_bounds__(256) void split_bf16(const float* __restrict__ x,
                                                  __nv_bfloat16* __restrict__ hi,
                                                  __nv_bfloat16* __restrict__ lo,
                                                  int n4) {
    int i = blockIdx.x * blockDim.x + threadIdx.x;
    if (i >= n4) return;
    float4 f = ((const float4*)x)[i];
    __nv_bfloat16 h[4], l[4];
    float v[4] = {f.x, f.y, f.z, f.w};
#pragma unroll
    for (int j = 0; j < 4; j++) {
        h[j] = __float2bfloat16_rn(v[j]);
        l[j] = __float2bfloat16_rn(v[j] - __bfloat162float(h[j]));
    }
    ((uint2*)hi)[i] = *(uint2*)h;
    ((uint2*)lo)[i] = *(uint2*)l;
}

// ===================================================================
// bf16 split-precision GEMM, chunked smem layout, 2-stage cp.async.
//   C[M,N] = A[M,K] @ B[N,K]^T, K=4096
// CTA 128x128, BK=32, 256 thr (8 warps 2x4), warp tile 64x32.
// stage = 32768 B, 2 stages = 65536 B -> 3 CTAs/SM.
// chunk16B idx within tile = (row&7) + 8*c + 32*(row>>3)
//  -> every ldmatrix reads 128 contiguous bytes (conflict-free).
// ===================================================================
#define TILE_B2   8192                 // 128 rows * 4 chunks * 16B
#define STAGE_B2  (4 * TILE_B2)        // Ah|Al|Bh|Bl = 32768
#define GEMM_SMEM (2 * STAGE_B2)       // 65536
#define KT_N      (GK / 32)            // 128

template <bool CLIP>
__global__ __launch_bounds__(256) void gemm_mma_split(
    const __nv_bfloat16* __restrict__ Ah, const __nv_bfloat16* __restrict__ Al,
    const __nv_bfloat16* __restrict__ Bh, const __nv_bfloat16* __restrict__ Bl,
    float* __restrict__ C, int N) {
    extern __shared__ char dsm[];
    const uint32_t sb = smem_u32(dsm);

    const int tid = threadIdx.x;
    const int wid = tid >> 5, lane = tid & 31;
    const int warp_m = wid & 1, warp_n = wid >> 1;
    const int m0 = blockIdx.y * 128, n0 = blockIdx.x * 128;

    const __nv_bfloat16* gsrc[4] = {
        Ah + (size_t)m0 * GK, Al + (size_t)m0 * GK,
        Bh + (size_t)n0 * GK, Bl + (size_t)n0 * GK};

    // per-lane ldmatrix base offsets (within stage); add ks*256 per k16 step
    const int g = lane >> 3, r = lane & 7;
    uint32_t a_off[4], b_off[2];
#pragma unroll
    for (int fm = 0; fm < 4; fm++)
        a_off[fm] = (uint32_t)((r + 32 * (warp_m * 8 + fm * 2 + (g & 1))) * 16
                               + (g >> 1) * 128);
#pragma unroll
    for (int nf = 0; nf < 2; nf++)
        b_off[nf] = (uint32_t)((r + 32 * (warp_n * 4 + nf * 2 + (g >> 1))) * 16
                               + (g & 1) * 128);

    float acc[4][4][4];
#pragma unroll
    for (int i = 0; i < 4; i++)
#pragma unroll
        for (int j = 0; j < 4; j++)
#pragma unroll
            for (int q = 0; q < 4; q++) acc[i][j][q] = 0.f;

    auto prefetch = [&](int kt) {
        const uint32_t so = sb + (uint32_t)(kt & 1) * STAGE_B2;
        const int k0 = kt * 32;
#pragma unroll
        for (int it = 0; it < 8; it++) {
            int gi = tid + it * 256;
            int tile = gi >> 9;
            int w = gi & 511;
            int row = w >> 2, c = w & 3;
            const char* src = (const char*)(gsrc[tile] + (size_t)row * GK + k0 + c * 8);
            uint32_t dst = so + (uint32_t)(tile * TILE_B2
                                           + ((row & 7) + 8 * c + 32 * (row >> 3)) * 16);
            asm volatile("cp.async.cg.shared.global [%0], [%1], 16;"
                         :: "r"(dst), "l"(src));
        }
        asm volatile("cp.async.commit_group;");
    };

    prefetch(0);

    for (int kt = 0; kt < KT_N; kt++) {
        if (kt + 1 < KT_N) {
            prefetch(kt + 1);
            asm volatile("cp.async.wait_group 1;");
        } else {
            asm volatile("cp.async.wait_group 0;");
        }
        __syncthreads();

        const uint32_t so = sb + (uint32_t)(kt & 1) * STAGE_B2;
#pragma unroll
        for (int ks = 0; ks < 2; ks++) {
            const uint32_t ko = (uint32_t)(ks * 256);
            uint32_t Af[4][4], Lf[4][4], Bf[2][4], Mf[2][4];
#pragma unroll
            for (int fm = 0; fm < 4; fm++) {
                ldsm4(so + a_off[fm] + ko, Af[fm]);
                ldsm4(so + TILE_B2 + a_off[fm] + ko, Lf[fm]);
            }
#pragma unroll
            for (int nf = 0; nf < 2; nf++) {
                ldsm4(so + 2 * TILE_B2 + b_off[nf] + ko, Bf[nf]);
                ldsm4(so + 3 * TILE_B2 + b_off[nf] + ko, Mf[nf]);
            }
#pragma unroll
            for (int fm = 0; fm < 4; fm++)
#pragma unroll
                for (int fn = 0; fn < 4; fn++) {
                    const int n2 = fn >> 1, j = (fn & 1) * 2;
                    mma_bf16(acc[fm][fn], Af[fm], Bf[n2][j], Bf[n2][j + 1]);
                    mma_bf16(acc[fm][fn], Af[fm], Mf[n2][j], Mf[n2][j + 1]);
                    mma_bf16(acc[fm][fn], Lf[fm], Bf[n2][j], Bf[n2][j + 1]);
                }
        }
        __syncthreads();
    }

    // epilogue: direct fp32 stores
    const int mrow = m0 + warp_m * 64 + (lane >> 2);
    const int ncol = n0 + warp_n * 32 + (lane & 3) * 2;
#pragma unroll
    for (int fm = 0; fm < 4; fm++)
#pragma unroll
        for (int fn = 0; fn < 4; fn++) {
            float* p0 = C + (size_t)(mrow + fm * 16) * N + ncol + fn * 8;
            float* p1 = p0 + (size_t)8 * N;
            float2 v0 = {acc[fm][fn][0], acc[fm][fn][1]};
            float2 v1 = {acc[fm][fn][2], acc[fm][fn][3]};
            if (CLIP) {
                v0.x = fminf(fmaxf(v0.x, -CLIP_V), CLIP_V);
                v0.y = fminf(fmaxf(v0.y, -CLIP_V), CLIP_V);
                v1.x = fminf(fmaxf(v1.x, -CLIP_V), CLIP_V);
                v1.y = fminf(fmaxf(v1.y, -CLIP_V), CLIP_V);
            }
            *(float2*)p0 = v0;
            *(float2*)p1 = v1;
        }
}

// ===================================================================
// RoPE + fp16 cast: qkv fp32 -> q16 [T][4096], k16/v16 [T][1024]
// ===================================================================
#define ROPE_TOTAL1 (T_TOK * 40 * 64)
#define ROPE_TOTAL2 (T_TOK * 1024)

__global__ void rope_cast(const float* __restrict__ qkv,
                          const float* __restrict__ cosp,
                          const float* __restrict__ sinp,
                          __half* __restrict__ q16,
                          __half* __restrict__ k16,
                          __half* __restrict__ v16) {
    int idx = blockIdx.x * blockDim.x + threadIdx.x;
    if (idx < ROPE_TOTAL1) {
        int d  = idx & 63;
        int rr = idx >> 6;
        int hh = rr % 40;
        int t  = rr / 40;
        size_t base = (size_t)t * QKV_OUT + (hh < 32 ? hh * 128 : 4096 + (hh - 32) * 128);
        float x1 = qkv[base + d];
        float x2 = qkv[base + 64 + d];
        float c = cosp[t * 64 + d];
        float s = sinp[t * 64 + d];
        float o1 = x1 * c - x2 * s;
        float o2 = x2 * c + x1 * s;
        if (hh < 32) {
            size_t ob = (size_t)t * 4096 + hh * 128;
            q16[ob + d]      = __float2half_rn(o1);
            q16[ob + 64 + d] = __float2half_rn(o2);
        } else {
            size_t ob = (size_t)t * 1024 + (hh - 32) * 128;
            k16[ob + d]      = __float2half_rn(o1);
            k16[ob + 64 + d] = __float2half_rn(o2);
        }
    } else if (idx < ROPE_TOTAL1 + ROPE_TOTAL2) {
        int j = idx - ROPE_TOTAL1;
        int t = j >> 10, d = j & 1023;
        v16[j] = __float2half_rn(qkv[(size_t)t * QKV_OUT + 5120 + d]);
    }
}

// ===================================================================
// Flash attention, fp16 mma.sync, varlen causal, GQA.
// grid (32 qtiles, 32 heads), 128 thr (4 warps; warp owns 16 q rows).
// KV tile 64. Online softmax in C-fragment layout. Writes bf16 hi/lo.
// ===================================================================
#define APAD 136
#define ATTN_SMEM (3 * 64 * APAD * 2)   // Qs, Ks, Vs = 52224 B

__global__ __launch_bounds__(128) void attn_mma(
    const __half* __restrict__ Q, const __half* __restrict__ K,
    const __half* __restrict__ V, const int* __restrict__ cu,
    __nv_bfloat16* __restrict__ ath, __nv_bfloat16* __restrict__ atl) {
    extern __shared__ __half hsm[];
    __half* Qs = hsm;
    __half* Ks = Qs + 64 * APAD;
    __half* Vs = Ks + 64 * APAD;

    const int tid = threadIdx.x, w = tid >> 5, lane = tid & 31;
    const int g = lane >> 3, r = lane & 7;
    const int qt = blockIdx.x, h = blockIdx.y;
    const int q0 = qt * 64, kh = h >> 2;

    int seg_start = 0;
#pragma unroll
    for (int s = 1; s < 4; s++) {
        int c = cu[s];
        if (q0 >= c) seg_start = c;
    }

    // load Q tile (64 x 128 fp16)
#pragma unroll
    for (int it = 0; it < 8; it++) {
        int gi = tid + it * 128;
        int row = gi >> 4, c = gi & 15;
        *(uint4*)&Qs[row * APAD + c * 8] =
            *(const uint4*)&Q[(size_t)(q0 + row) * 4096 + h * 128 + c * 8];
    }

    const uint32_t q_off = smem_u32(Qs)
        + (uint32_t)(((w * 16 + (g & 1) * 8 + r) * APAD + (g >> 1) * 8) * 2);
    const uint32_t k_off = smem_u32(Ks)
        + (uint32_t)((((g >> 1) * 8 + r) * APAD + (g & 1) * 8) * 2);
    const uint32_t v_off = smem_u32(Vs)
        + (uint32_t)((((g & 1) * 8 + r) * APAD + (g >> 1) * 8) * 2);

    float Oa[16][4];
#pragma unroll
    for (int i = 0; i < 16; i++)
#pragma unroll
        for (int j = 0; j < 4; j++) Oa[i][j] = 0.f;
    float m0 = -1e30f, m1 = -1e30f, l0 = 0.f, l1 = 0.f;
    const int row0 = q0 + w * 16 + (lane >> 2), row1 = row0 + 8;
    const float sc = 0.08838834764831845f * 1.4426950408889634f;  // scale*log2e

    for (int kstart = seg_start; kstart < q0 + 64; kstart += 64) {
        __syncthreads();
#pragma unroll
        for (int it = 0; it < 8; it++) {
            int gi = tid + it * 128;
            int row = gi >> 4, c = gi & 15;
            size_t gb = (size_t)(kstart + row) * 1024 + kh * 128 + c * 8;
            *(uint4*)&Ks[row * APAD + c * 8] = *(const uint4*)&K[gb];
            *(uint4*)&Vs[row * APAD + c * 8] = *(const uint4*)&V[gb];
        }
        __syncthreads();

        // ---- S = Q K^T ----
        float Sa[8][4];
#pragma unroll
        for (int i = 0; i < 8; i++)
#pragma unroll
            for (int j = 0; j < 4; j++) Sa[i][j] = 0.f;
#pragma unroll
        for (int kstep = 0; kstep < 8; kstep++) {
            uint32_t qf[4];
            ldsm4(q_off + kstep * 32, qf);
#pragma unroll
            for (int nb16 = 0; nb16 < 4; nb16++) {
                uint32_t kf[4];
                ldsm4(k_off + nb16 * (16 * APAD * 2) + kstep * 32, kf);
                mma_fp16(Sa[2 * nb16], qf, kf[0], kf[1]);
                mma_fp16(Sa[2 * nb16 + 1], qf, kf[2], kf[3]);
            }
        }

        // scale to log2 domain + causal mask (only last tile)
#pragma unroll
        for (int nb = 0; nb < 8; nb++)
#pragma unroll
            for (int e = 0; e < 4; e++) Sa[nb][e] *= sc;
        if (kstart == q0) {
#pragma unroll
            for (int nb = 0; nb < 8; nb++) {
                int cg = kstart + nb * 8 + 2 * (lane & 3);
                if (cg > row0)     Sa[nb][0] = -1e30f;
                if (cg + 1 > row0) Sa[nb][1] = -1e30f;
                if (cg > row1)     Sa[nb][2] = -1e30f;
                if (cg + 1 > row1) Sa[nb][3] = -1e30f;
            }
        }

        // ---- online softmax ----
        float mx0 = -1e30f, mx1 = -1e30f;
#pragma unroll
        for (int nb = 0; nb < 8; nb++) {
            mx0 = fmaxf(mx0, fmaxf(Sa[nb][0], Sa[nb][1]));
            mx1 = fmaxf(mx1, fmaxf(Sa[nb][2], Sa[nb][3]));
        }
        mx0 = fmaxf(mx0, __shfl_xor_sync(0xffffffffu, mx0, 1));
        mx0 = fmaxf(mx0, __shfl_xor_sync(0xffffffffu, mx0, 2));
        mx1 = fmaxf(mx1, __shfl_xor_sync(0xffffffffu, mx1, 1));
        mx1 = fmaxf(mx1, __shfl_xor_sync(0xffffffffu, mx1, 2));
        float mn0 = fmaxf(m0, mx0), mn1 = fmaxf(m1, mx1);
        float c0 = exp2f(m0 - mn0), c1 = exp2f(m1 - mn1);
        m0 = mn0;
        m1 = mn1;
        float s0 = 0.f, s1 = 0.f;
        uint32_t pA[8], pB[8];
#pragma unroll
        for (int nb = 0; nb < 8; nb++) {
            float p0 = exp2f(Sa[nb][0] - mn0);
            float p1 = exp2f(Sa[nb][1] - mn0);
            float p2 = exp2f(Sa[nb][2] - mn1);
            float p3 = exp2f(Sa[nb][3] - mn1);
            s0 += p0 + p1;
            s1 += p2 + p3;
            pA[nb] = pack_half2(p0, p1);
            pB[nb] = pack_half2(p2, p3);
        }
        s0 += __shfl_xor_sync(0xffffffffu, s0, 1);
        s0 += __shfl_xor_sync(0xffffffffu, s0, 2);
        s1 += __shfl_xor_sync(0xffffffffu, s1, 1);
        s1 += __shfl_xor_sync(0xffffffffu, s1, 2);
        l0 = l0 * c0 + s0;
        l1 = l1 * c1 + s1;
#pragma unroll
        for (int db = 0; db < 16; db++) {
            Oa[db][0] *= c0;
            Oa[db][1] *= c0;
            Oa[db][2] *= c1;
            Oa[db][3] *= c1;
        }

        // ---- O += P V ----
#pragma unroll
        for (int ks2 = 0; ks2 < 4; ks2++) {
            uint32_t af[4] = {pA[2 * ks2], pB[2 * ks2],
                              pA[2 * ks2 + 1], pB[2 * ks2 + 1]};
#pragma unroll
            for (int db16 = 0; db16 < 8; db16++) {
                uint32_t vf[4];
                ldsm4t(v_off + ks2 * (16 * APAD * 2) + db16 * 32, vf);
                mma_fp16(Oa[2 * db16], af, vf[0], vf[1]);
                mma_fp16(Oa[2 * db16 + 1], af, vf[2], vf[3]);
            }
        }
    }

    // epilogue: normalize, write bf16 hi/lo directly
    float i0 = 1.f / l0, i1 = 1.f / l1;
#pragma unroll
    for (int db = 0; db < 16; db++) {
        int col = h * 128 + db * 8 + (lane & 3) * 2;
        float x0 = Oa[db][0] * i0, x1 = Oa[db][1] * i0;
        float x2 = Oa[db][2] * i1, x3 = Oa[db][3] * i1;
        __nv_bfloat16 h0 = __float2bfloat16_rn(x0);
        __nv_bfloat16 h1 = __float2bfloat16_rn(x1);
        __nv_bfloat16 h2 = __float2bfloat16_rn(x2);
        __nv_bfloat16 h3 = __float2bfloat16_rn(x3);
        __nv_bfloat16 e0 = __float2bfloat16_rn(x0 - __bfloat162float(h0));
        __nv_bfloat16 e1 = __float2bfloat16_rn(x1 - __bfloat162float(h1));
        __nv_bfloat16 e2 = __float2bfloat16_rn(x2 - __bfloat162float(h2));
        __nv_bfloat16 e3 = __float2bfloat16_rn(x3 - __bfloat162float(h3));
        uint32_t uh0 = ((uint32_t)__bfloat16_as_ushort(h1) << 16) | __bfloat16_as_ushort(h0);
        uint32_t uh1 = ((uint32_t)__bfloat16_as_ushort(h3) << 16) | __bfloat16_as_ushort(h2);
        uint32_t ul0 = ((uint32_t)__bfloat16_as_ushort(e1) << 16) | __bfloat16_as_ushort(e0);
        uint32_t ul1 = ((uint32_t)__bfloat16_as_ushort(e3) << 16) | __bfloat16_as_ushort(e2);
        *(uint32_t*)&ath[(size_t)row0 * 4096 + col] = uh0;
        *(uint32_t*)&ath[(size_t)row1 * 4096 + col] = uh1;
        *(uint32_t*)&atl[(size_t)row0 * 4096 + col] = ul0;
        *(uint32_t*)&atl[(size_t)row1 * 4096 + col] = ul1;
    }
}

// ===================================================================
// launch
// ===================================================================
extern "C" void kernel_launch(void* const* d_in, const int* in_sizes, int n_in,
                              void* d_out, int out_size) {
    const float* hidden = (const float*)d_in[0];
    const float* w_qkv  = (const float*)d_in[1];
    const float* w_o    = (const float*)d_in[2];
    const float* cosp   = (const float*)d_in[3];
    const float* sinp   = (const float*)d_in[4];
    const int*   cu     = (const int*)d_in[5];
    float* out = (float*)d_out;

    float* qkvp;
    __nv_bfloat16 *hh, *hl, *wqh, *wql, *woh, *wol, *ath, *atl;
    __half *q16, *k16, *v16;
    cudaGetSymbolAddress((void**)&qkvp, g_qkv);
    cudaGetSymbolAddress((void**)&hh,  g_hid_h);
    cudaGetSymbolAddress((void**)&hl,  g_hid_l);
    cudaGetSymbolAddress((void**)&wqh, g_wqkv_h);
    cudaGetSymbolAddress((void**)&wql, g_wqkv_l);
    cudaGetSymbolAddress((void**)&woh, g_wo_h);
    cudaGetSymbolAddress((void**)&wol, g_wo_l);
    cudaGetSymbolAddress((void**)&ath, g_att_h);
    cudaGetSymbolAddress((void**)&atl, g_att_l);
    cudaGetSymbolAddress((void**)&q16, g_q16);
    cudaGetSymbolAddress((void**)&k16, g_k16);
    cudaGetSymbolAddress((void**)&v16, g_v16);

    cudaFuncSetAttribute(gemm_mma_split<true>,
                         cudaFuncAttributeMaxDynamicSharedMemorySize, GEMM_SMEM);
    cudaFuncSetAttribute(gemm_mma_split<false>,
                         cudaFuncAttributeMaxDynamicSharedMemorySize, GEMM_SMEM);
    cudaFuncSetAttribute(attn_mma,
                         cudaFuncAttributeMaxDynamicSharedMemorySize, ATTN_SMEM);

    // 0) split inputs/weights into bf16 hi/lo
    {
        int n4;
        n4 = T_TOK * D_MODEL / 4;
        split_bf16<<<(n4 + 255) / 256, 256>>>(hidden, hh, hl, n4);
        n4 = QKV_OUT * D_MODEL / 4;
        split_bf16<<<(n4 + 255) / 256, 256>>>(w_qkv, wqh, wql, n4);
        n4 = D_MODEL * D_MODEL / 4;
        split_bf16<<<(n4 + 255) / 256, 256>>>(w_o, woh, wol, n4);
    }
    // 1) QKV projection + clip
    gemm_mma_split<true><<<dim3(QKV_OUT / 128, T_TOK / 128), 256, GEMM_SMEM>>>(
        hh, hl, wqh, wql, qkvp, QKV_OUT);
    // 2) RoPE + fp16 cast
    {
        int total = ROPE_TOTAL1 + ROPE_TOTAL2;
        rope_cast<<<(total + 255) / 256, 256>>>(qkvp, cosp, sinp, q16, k16, v16);
    }
    // 3) attention (fp16 tensor cores) -> bf16 hi/lo directly
    attn_mma<<<dim3(T_TOK / 64, N_HEADS), 128, ATTN_SMEM>>>(q16, k16, v16, cu,
                                                            ath, atl);
    // 4) output projection
    gemm_mma_split<false><<<dim3(D_MODEL / 128, T_TOK / 128), 256, GEMM_SMEM>>>(
        ath, atl, woh, wol, out, D_MODEL);
}

// round 11
// speedup vs baseline: 2.0328x; 2.0328x over previous
#include <cuda_runtime.h>
#include <cuda_bf16.h>
#include <cuda_fp16.h>
#include <math.h>
#include <stdint.h>

// ---------------- problem constants ----------------
#define T_TOK   2048
#define D_MODEL 4096
#define N_HEADS 32
#define KV_HEADS 8
#define HEAD_DIM 128
#define QKV_OUT 6144
#define CLIP_V  8.0f
#define GK      4096

// ---------------- scratch (device globals; no allocations) ----------------
__device__ float g_qkv[(size_t)T_TOK * QKV_OUT];

__device__ __nv_bfloat16 g_hid_h[(size_t)T_TOK * D_MODEL];
__device__ __nv_bfloat16 g_hid_l[(size_t)T_TOK * D_MODEL];
__device__ __nv_bfloat16 g_wqkv_h[(size_t)QKV_OUT * D_MODEL];
__device__ __nv_bfloat16 g_wqkv_l[(size_t)QKV_OUT * D_MODEL];
__device__ __nv_bfloat16 g_wo_h[(size_t)D_MODEL * D_MODEL];
__device__ __nv_bfloat16 g_wo_l[(size_t)D_MODEL * D_MODEL];
__device__ __nv_bfloat16 g_att_h[(size_t)T_TOK * D_MODEL];
__device__ __nv_bfloat16 g_att_l[(size_t)T_TOK * D_MODEL];

__device__ __half g_q16[(size_t)T_TOK * D_MODEL];
__device__ __half g_k16[(size_t)T_TOK * KV_HEADS * HEAD_DIM];
__device__ __half g_v16[(size_t)T_TOK * KV_HEADS * HEAD_DIM];

// ---------------- helpers ----------------
__device__ __forceinline__ uint32_t smem_u32(const void* p) {
    uint32_t a;
    asm("{ .reg .u64 t; cvta.to.shared.u64 t, %1; cvt.u32.u64 %0, t; }"
        : "=r"(a) : "l"(p));
    return a;
}
__device__ __forceinline__ void ldsm4(uint32_t addr, uint32_t* r) {
    asm volatile("ldmatrix.sync.aligned.m8n8.x4.shared.b16 {%0,%1,%2,%3}, [%4];"
                 : "=r"(r[0]), "=r"(r[1]), "=r"(r[2]), "=r"(r[3]) : "r"(addr));
}
__device__ __forceinline__ void ldsm4t(uint32_t addr, uint32_t* r) {
    asm volatile("ldmatrix.sync.aligned.m8n8.x4.trans.shared.b16 {%0,%1,%2,%3}, [%4];"
                 : "=r"(r[0]), "=r"(r[1]), "=r"(r[2]), "=r"(r[3]) : "r"(addr));
}
__device__ __forceinline__ void mma_bf16(float* d, const uint32_t* a,
                                         uint32_t b0, uint32_t b1) {
    asm volatile(
        "mma.sync.aligned.m16n8k16.row.col.f32.bf16.bf16.f32 "
        "{%0,%1,%2,%3}, {%4,%5,%6,%7}, {%8,%9}, {%0,%1,%2,%3};"
        : "+f"(d[0]), "+f"(d[1]), "+f"(d[2]), "+f"(d[3])
        : "r"(a[0]), "r"(a[1]), "r"(a[2]), "r"(a[3]), "r"(b0), "r"(b1));
}
__device__ __forceinline__ void mma_fp16(float* d, const uint32_t* a,
                                         uint32_t b0, uint32_t b1) {
    asm volatile(
        "mma.sync.aligned.m16n8k16.row.col.f32.f16.f16.f32 "
        "{%0,%1,%2,%3}, {%4,%5,%6,%7}, {%8,%9}, {%0,%1,%2,%3};"
        : "+f"(d[0]), "+f"(d[1]), "+f"(d[2]), "+f"(d[3])
        : "r"(a[0]), "r"(a[1]), "r"(a[2]), "r"(a[3]), "r"(b0), "r"(b1));
}
__device__ __forceinline__ uint32_t pack_half2(float lo, float hi) {
    uint32_t u;
    asm("cvt.rn.f16x2.f32 %0, %1, %2;" : "=r"(u) : "f"(hi), "f"(lo));
    return u;
}

// ===================================================================
// Split fp32 -> (hi, lo) bf16
// ===================================================================
__global__ __launch_bounds__(256) void split_bf16(const float* __restrict__ x,
                                                  __nv_bfloat16* __restrict__ hi,
                                                  __nv_bfloat16* __restrict__ lo,
                                                  int n4) {
    int i = blockIdx.x * blockDim.x + threadIdx.x;
    if (i >= n4) return;
    float4 f = ((const float4*)x)[i];
    __nv_bfloat16 h[4], l[4];
    float v[4] = {f.x, f.y, f.z, f.w};
#pragma unroll
    for (int j = 0; j < 4; j++) {
        h[j] = __float2bfloat16_rn(v[j]);
        l[j] = __float2bfloat16_rn(v[j] - __bfloat162float(h[j]));
    }
    ((uint2*)hi)[i] = *(uint2*)h;
    ((uint2*)lo)[i] = *(uint2*)l;
}

// ===================================================================
// bf16 split-precision GEMM via mma.sync  (EXACT R4 version, proven
// 907us / tensor 56%):  C[M,N] = A[M,K] @ B[N,K]^T, K=4096
// CTA 128x128, BK=32, 256 thr (8 warps 2x4), warp tile 64x32.
// smem rows padded to 40 bf16 (80B).
// ===================================================================
#define PADK       40
#define TILE_BY    (128 * PADK * 2)        // 10240 B per matrix tile
#define STAGE_BY   (4 * TILE_BY)           // Ah|Al|Bh|Bl = 40960 B
#define GEMM_SMEM  (2 * STAGE_BY)          // 81920 B
#define KT_N       (GK / 32)               // 128

template <bool CLIP>
__global__ __launch_bounds__(256) void gemm_mma_split(
    const __nv_bfloat16* __restrict__ Ah, const __nv_bfloat16* __restrict__ Al,
    const __nv_bfloat16* __restrict__ Bh, const __nv_bfloat16* __restrict__ Bl,
    float* __restrict__ C, int N) {
    extern __shared__ char dsm[];
    const uint32_t sb = smem_u32(dsm);

    const int tid = threadIdx.x;
    const int wid = tid >> 5, lane = tid & 31;
    const int warp_m = wid & 1, warp_n = wid >> 1;
    const int m0 = blockIdx.y * 128, n0 = blockIdx.x * 128;

    const __nv_bfloat16* gsrc[4] = {
        Ah + (size_t)m0 * GK, Al + (size_t)m0 * GK,
        Bh + (size_t)n0 * GK, Bl + (size_t)n0 * GK};

    // ldmatrix per-lane byte offsets (within a stage)
    const int g = lane >> 3, r = lane & 7;
    uint32_t a_off[4], b_off[2];
#pragma unroll
    for (int fm = 0; fm < 4; fm++)
        a_off[fm] = (uint32_t)((warp_m * 64 + fm * 16 + (g & 1) * 8 + r) * (PADK * 2)
                               + (g >> 1) * 16);
#pragma unroll
    for (int nf = 0; nf < 2; nf++)
        b_off[nf] = (uint32_t)((warp_n * 32 + nf * 16 + (g >> 1) * 8 + r) * (PADK * 2)
                               + (g & 1) * 16);

    float acc[4][4][4];
#pragma unroll
    for (int i = 0; i < 4; i++)
#pragma unroll
        for (int j = 0; j < 4; j++)
#pragma unroll
            for (int q = 0; q < 4; q++) acc[i][j][q] = 0.f;

    // cp.async prefetch of one BK=32 stage
    auto prefetch = [&](int kt) {
        const uint32_t so = sb + (uint32_t)(kt & 1) * STAGE_BY;
        const int k0 = kt * 32;
#pragma unroll
        for (int it = 0; it < 8; it++) {
            int gi = tid + it * 256;
            int tile = gi >> 9;
            int w = gi & 511;
            int row = w >> 2, c = w & 3;
            const char* src = (const char*)(gsrc[tile] + (size_t)row * GK + k0 + c * 8);
            uint32_t dst = so + (uint32_t)(tile * TILE_BY + row * (PADK * 2) + c * 16);
            asm volatile("cp.async.cg.shared.global [%0], [%1], 16;"
                         :: "r"(dst), "l"(src));
        }
        asm volatile("cp.async.commit_group;");
    };

    prefetch(0);

    for (int kt = 0; kt < KT_N; kt++) {
        if (kt + 1 < KT_N) {
            prefetch(kt + 1);
            asm volatile("cp.async.wait_group 1;");
        } else {
            asm volatile("cp.async.wait_group 0;");
        }
        __syncthreads();

        const uint32_t so = sb + (uint32_t)(kt & 1) * STAGE_BY;
#pragma unroll
        for (int ks = 0; ks < 2; ks++) {
            const uint32_t ko = (uint32_t)(ks * 32);
            uint32_t Af[4][4], Lf[4][4], Bf[2][4], Mf[2][4];
#pragma unroll
            for (int fm = 0; fm < 4; fm++) {
                ldsm4(so + a_off[fm] + ko, Af[fm]);
                ldsm4(so + TILE_BY + a_off[fm] + ko, Lf[fm]);
            }
#pragma unroll
            for (int nf = 0; nf < 2; nf++) {
                ldsm4(so + 2 * TILE_BY + b_off[nf] + ko, Bf[nf]);
                ldsm4(so + 3 * TILE_BY + b_off[nf] + ko, Mf[nf]);
            }
#pragma unroll
            for (int fm = 0; fm < 4; fm++)
#pragma unroll
                for (int fn = 0; fn < 4; fn++) {
                    const int n2 = fn >> 1, j = (fn & 1) * 2;
                    mma_bf16(acc[fm][fn], Af[fm], Bf[n2][j], Bf[n2][j + 1]);
                    mma_bf16(acc[fm][fn], Af[fm], Mf[n2][j], Mf[n2][j + 1]);
                    mma_bf16(acc[fm][fn], Lf[fm], Bf[n2][j], Bf[n2][j + 1]);
                }
        }
        __syncthreads();
    }

    // epilogue: direct fp32 stores (float2 per fragment row)
    const int mrow = m0 + warp_m * 64 + (lane >> 2);
    const int ncol = n0 + warp_n * 32 + (lane & 3) * 2;
#pragma unroll
    for (int fm = 0; fm < 4; fm++)
#pragma unroll
        for (int fn = 0; fn < 4; fn++) {
            float* p0 = C + (size_t)(mrow + fm * 16) * N + ncol + fn * 8;
            float* p1 = p0 + (size_t)8 * N;
            float2 v0 = {acc[fm][fn][0], acc[fm][fn][1]};
            float2 v1 = {acc[fm][fn][2], acc[fm][fn][3]};
            if (CLIP) {
                v0.x = fminf(fmaxf(v0.x, -CLIP_V), CLIP_V);
                v0.y = fminf(fmaxf(v0.y, -CLIP_V), CLIP_V);
                v1.x = fminf(fmaxf(v1.x, -CLIP_V), CLIP_V);
                v1.y = fminf(fmaxf(v1.y, -CLIP_V), CLIP_V);
            }
            *(float2*)p0 = v0;
            *(float2*)p1 = v1;
        }
}

// ===================================================================
// RoPE + fp16 cast: qkv fp32 -> q16 [T][4096], k16/v16 [T][1024]
// ===================================================================
#define ROPE_TOTAL1 (T_TOK * 40 * 64)
#define ROPE_TOTAL2 (T_TOK * 1024)

__global__ void rope_cast(const float* __restrict__ qkv,
                          const float* __restrict__ cosp,
                          const float* __restrict__ sinp,
                          __half* __restrict__ q16,
                          __half* __restrict__ k16,
                          __half* __restrict__ v16) {
    int idx = blockIdx.x * blockDim.x + threadIdx.x;
    if (idx < ROPE_TOTAL1) {
        int d  = idx & 63;
        int rr = idx >> 6;
        int hh = rr % 40;
        int t  = rr / 40;
        size_t base = (size_t)t * QKV_OUT + (hh < 32 ? hh * 128 : 4096 + (hh - 32) * 128);
        float x1 = qkv[base + d];
        float x2 = qkv[base + 64 + d];
        float c = cosp[t * 64 + d];
        float s = sinp[t * 64 + d];
        float o1 = x1 * c - x2 * s;
        float o2 = x2 * c + x1 * s;
        if (hh < 32) {
            size_t ob = (size_t)t * 4096 + hh * 128;
            q16[ob + d]      = __float2half_rn(o1);
            q16[ob + 64 + d] = __float2half_rn(o2);
        } else {
            size_t ob = (size_t)t * 1024 + (hh - 32) * 128;
            k16[ob + d]      = __float2half_rn(o1);
            k16[ob + 64 + d] = __float2half_rn(o2);
        }
    } else if (idx < ROPE_TOTAL1 + ROPE_TOTAL2) {
        int j = idx - ROPE_TOTAL1;
        int t = j >> 10, d = j & 1023;
        v16[j] = __float2half_rn(qkv[(size_t)t * QKV_OUT + 5120 + d]);
    }
}

// ===================================================================
// Flash attention, fp16 mma.sync, varlen causal, GQA.
// grid (32 qtiles, 32 heads), 128 thr (4 warps; warp owns 16 q rows).
// KV tile 64. Online softmax in C-fragment layout. Writes bf16 hi/lo.
// ===================================================================
#define APAD 136
#define ATTN_SMEM (3 * 64 * APAD * 2)   // Qs, Ks, Vs = 52224 B

__global__ __launch_bounds__(128) void attn_mma(
    const __half* __restrict__ Q, const __half* __restrict__ K,
    const __half* __restrict__ V, const int* __restrict__ cu,
    __nv_bfloat16* __restrict__ ath, __nv_bfloat16* __restrict__ atl) {
    extern __shared__ __half hsm[];
    __half* Qs = hsm;
    __half* Ks = Qs + 64 * APAD;
    __half* Vs = Ks + 64 * APAD;

    const int tid = threadIdx.x, w = tid >> 5, lane = tid & 31;
    const int g = lane >> 3, r = lane & 7;
    const int qt = blockIdx.x, h = blockIdx.y;
    const int q0 = qt * 64, kh = h >> 2;

    int seg_start = 0;
#pragma unroll
    for (int s = 1; s < 4; s++) {
        int c = cu[s];
        if (q0 >= c) seg_start = c;
    }

    // load Q tile (64 x 128 fp16)
#pragma unroll
    for (int it = 0; it < 8; it++) {
        int gi = tid + it * 128;
        int row = gi >> 4, c = gi & 15;
        *(uint4*)&Qs[row * APAD + c * 8] =
            *(const uint4*)&Q[(size_t)(q0 + row) * 4096 + h * 128 + c * 8];
    }

    const uint32_t q_off = smem_u32(Qs)
        + (uint32_t)(((w * 16 + (g & 1) * 8 + r) * APAD + (g >> 1) * 8) * 2);
    const uint32_t k_off = smem_u32(Ks)
        + (uint32_t)((((g >> 1) * 8 + r) * APAD + (g & 1) * 8) * 2);
    const uint32_t v_off = smem_u32(Vs)
        + (uint32_t)((((g & 1) * 8 + r) * APAD + (g >> 1) * 8) * 2);

    float Oa[16][4];
#pragma unroll
    for (int i = 0; i < 16; i++)
#pragma unroll
        for (int j = 0; j < 4; j++) Oa[i][j] = 0.f;
    float m0 = -1e30f, m1 = -1e30f, l0 = 0.f, l1 = 0.f;
    const int row0 = q0 + w * 16 + (lane >> 2), row1 = row0 + 8;
    const float sc = 0.08838834764831845f * 1.4426950408889634f;  // scale*log2e

    for (int kstart = seg_start; kstart < q0 + 64; kstart += 64) {
        __syncthreads();
#pragma unroll
        for (int it = 0; it < 8; it++) {
            int gi = tid + it * 128;
            int row = gi >> 4, c = gi & 15;
            size_t gb = (size_t)(kstart + row) * 1024 + kh * 128 + c * 8;
            *(uint4*)&Ks[row * APAD + c * 8] = *(const uint4*)&K[gb];
            *(uint4*)&Vs[row * APAD + c * 8] = *(const uint4*)&V[gb];
        }
        __syncthreads();

        // ---- S = Q K^T ----
        float Sa[8][4];
#pragma unroll
        for (int i = 0; i < 8; i++)
#pragma unroll
            for (int j = 0; j < 4; j++) Sa[i][j] = 0.f;
#pragma unroll
        for (int kstep = 0; kstep < 8; kstep++) {
            uint32_t qf[4];
            ldsm4(q_off + kstep * 32, qf);
#pragma unroll
            for (int nb16 = 0; nb16 < 4; nb16++) {
                uint32_t kf[4];
                ldsm4(k_off + nb16 * (16 * APAD * 2) + kstep * 32, kf);
                mma_fp16(Sa[2 * nb16], qf, kf[0], kf[1]);
                mma_fp16(Sa[2 * nb16 + 1], qf, kf[2], kf[3]);
            }
        }

        // scale to log2 domain + causal mask (only last tile)
#pragma unroll
        for (int nb = 0; nb < 8; nb++)
#pragma unroll
            for (int e = 0; e < 4; e++) Sa[nb][e] *= sc;
        if (kstart == q0) {
#pragma unroll
            for (int nb = 0; nb < 8; nb++) {
                int cg = kstart + nb * 8 + 2 * (lane & 3);
                if (cg > row0)     Sa[nb][0] = -1e30f;
                if (cg + 1 > row0) Sa[nb][1] = -1e30f;
                if (cg > row1)     Sa[nb][2] = -1e30f;
                if (cg + 1 > row1) Sa[nb][3] = -1e30f;
            }
        }

        // ---- online softmax ----
        float mx0 = -1e30f, mx1 = -1e30f;
#pragma unroll
        for (int nb = 0; nb < 8; nb++) {
            mx0 = fmaxf(mx0, fmaxf(Sa[nb][0], Sa[nb][1]));
            mx1 = fmaxf(mx1, fmaxf(Sa[nb][2], Sa[nb][3]));
        }
        mx0 = fmaxf(mx0, __shfl_xor_sync(0xffffffffu, mx0, 1));
        mx0 = fmaxf(mx0, __shfl_xor_sync(0xffffffffu, mx0, 2));
        mx1 = fmaxf(mx1, __shfl_xor_sync(0xffffffffu, mx1, 1));
        mx1 = fmaxf(mx1, __shfl_xor_sync(0xffffffffu, mx1, 2));
        float mn0 = fmaxf(m0, mx0), mn1 = fmaxf(m1, mx1);
        float c0 = exp2f(m0 - mn0), c1 = exp2f(m1 - mn1);
        m0 = mn0;
        m1 = mn1;
        float s0 = 0.f, s1 = 0.f;
        uint32_t pA[8], pB[8];
#pragma unroll
        for (int nb = 0; nb < 8; nb++) {
            float p0 = exp2f(Sa[nb][0] - mn0);
            float p1 = exp2f(Sa[nb][1] - mn0);
            float p2 = exp2f(Sa[nb][2] - mn1);
            float p3 = exp2f(Sa[nb][3] - mn1);
            s0 += p0 + p1;
            s1 += p2 + p3;
            pA[nb] = pack_half2(p0, p1);
            pB[nb] = pack_half2(p2, p3);
        }
        s0 += __shfl_xor_sync(0xffffffffu, s0, 1);
        s0 += __shfl_xor_sync(0xffffffffu, s0, 2);
        s1 += __shfl_xor_sync(0xffffffffu, s1, 1);
        s1 += __shfl_xor_sync(0xffffffffu, s1, 2);
        l0 = l0 * c0 + s0;
        l1 = l1 * c1 + s1;
#pragma unroll
        for (int db = 0; db < 16; db++) {
            Oa[db][0] *= c0;
            Oa[db][1] *= c0;
            Oa[db][2] *= c1;
            Oa[db][3] *= c1;
        }

        // ---- O += P V ----
#pragma unroll
        for (int ks2 = 0; ks2 < 4; ks2++) {
            uint32_t af[4] = {pA[2 * ks2], pB[2 * ks2],
                              pA[2 * ks2 + 1], pB[2 * ks2 + 1]};
#pragma unroll
            for (int db16 = 0; db16 < 8; db16++) {
                uint32_t vf[4];
                ldsm4t(v_off + ks2 * (16 * APAD * 2) + db16 * 32, vf);
                mma_fp16(Oa[2 * db16], af, vf[0], vf[1]);
                mma_fp16(Oa[2 * db16 + 1], af, vf[2], vf[3]);
            }
        }
    }

    // epilogue: normalize, write bf16 hi/lo directly
    float i0 = 1.f / l0, i1 = 1.f / l1;
#pragma unroll
    for (int db = 0; db < 16; db++) {
        int col = h * 128 + db * 8 + (lane & 3) * 2;
        float x0 = Oa[db][0] * i0, x1 = Oa[db][1] * i0;
        float x2 = Oa[db][2] * i1, x3 = Oa[db][3] * i1;
        __nv_bfloat16 h0 = __float2bfloat16_rn(x0);
        __nv_bfloat16 h1 = __float2bfloat16_rn(x1);
        __nv_bfloat16 h2 = __float2bfloat16_rn(x2);
        __nv_bfloat16 h3 = __float2bfloat16_rn(x3);
        __nv_bfloat16 e0 = __float2bfloat16_rn(x0 - __bfloat162float(h0));
        __nv_bfloat16 e1 = __float2bfloat16_rn(x1 - __bfloat162float(h1));
        __nv_bfloat16 e2 = __float2bfloat16_rn(x2 - __bfloat162float(h2));
        __nv_bfloat16 e3 = __float2bfloat16_rn(x3 - __bfloat162float(h3));
        uint32_t uh0 = ((uint32_t)__bfloat16_as_ushort(h1) << 16) | __bfloat16_as_ushort(h0);
        uint32_t uh1 = ((uint32_t)__bfloat16_as_ushort(h3) << 16) | __bfloat16_as_ushort(h2);
        uint32_t ul0 = ((uint32_t)__bfloat16_as_ushort(e1) << 16) | __bfloat16_as_ushort(e0);
        uint32_t ul1 = ((uint32_t)__bfloat16_as_ushort(e3) << 16) | __bfloat16_as_ushort(e2);
        *(uint32_t*)&ath[(size_t)row0 * 4096 + col] = uh0;
        *(uint32_t*)&ath[(size_t)row1 * 4096 + col] = uh1;
        *(uint32_t*)&atl[(size_t)row0 * 4096 + col] = ul0;
        *(uint32_t*)&atl[(size_t)row1 * 4096 + col] = ul1;
    }
}

// ===================================================================
// launch
// ===================================================================
extern "C" void kernel_launch(void* const* d_in, const int* in_sizes, int n_in,
                              void* d_out, int out_size) {
    const float* hidden = (const float*)d_in[0];
    const float* w_qkv  = (const float*)d_in[1];
    const float* w_o    = (const float*)d_in[2];
    const float* cosp   = (const float*)d_in[3];
    const float* sinp   = (const float*)d_in[4];
    const int*   cu     = (const int*)d_in[5];
    float* out = (float*)d_out;

    float* qkvp;
    __nv_bfloat16 *hh, *hl, *wqh, *wql, *woh, *wol, *ath, *atl;
    __half *q16, *k16, *v16;
    cudaGetSymbolAddress((void**)&qkvp, g_qkv);
    cudaGetSymbolAddress((void**)&hh,  g_hid_h);
    cudaGetSymbolAddress((void**)&hl,  g_hid_l);
    cudaGetSymbolAddress((void**)&wqh, g_wqkv_h);
    cudaGetSymbolAddress((void**)&wql, g_wqkv_l);
    cudaGetSymbolAddress((void**)&woh, g_wo_h);
    cudaGetSymbolAddress((void**)&wol, g_wo_l);
    cudaGetSymbolAddress((void**)&ath, g_att_h);
    cudaGetSymbolAddress((void**)&atl, g_att_l);
    cudaGetSymbolAddress((void**)&q16, g_q16);
    cudaGetSymbolAddress((void**)&k16, g_k16);
    cudaGetSymbolAddress((void**)&v16, g_v16);

    cudaFuncSetAttribute(gemm_mma_split<true>,
                         cudaFuncAttributeMaxDynamicSharedMemorySize, GEMM_SMEM);
    cudaFuncSetAttribute(gemm_mma_split<false>,
                         cudaFuncAttributeMaxDynamicSharedMemorySize, GEMM_SMEM);
    cudaFuncSetAttribute(attn_mma,
                         cudaFuncAttributeMaxDynamicSharedMemorySize, ATTN_SMEM);

    // 0) split inputs/weights into bf16 hi/lo
    {
        int n4;
        n4 = T_TOK * D_MODEL / 4;
        split_bf16<<<(n4 + 255) / 256, 256>>>(hidden, hh, hl, n4);
        n4 = QKV_OUT * D_MODEL / 4;
        split_bf16<<<(n4 + 255) / 256, 256>>>(w_qkv, wqh, wql, n4);
        n4 = D_MODEL * D_MODEL / 4;
        split_bf16<<<(n4 + 255) / 256, 256>>>(w_o, woh, wol, n4);
    }
    // 1) QKV projection + clip (R4-proven GEMM)
    gemm_mma_split<true><<<dim3(QKV_OUT / 128, T_TOK / 128), 256, GEMM_SMEM>>>(
        hh, hl, wqh, wql, qkvp, QKV_OUT);
    // 2) RoPE + fp16 cast
    {
        int total = ROPE_TOTAL1 + ROPE_TOTAL2;
        rope_cast<<<(total + 255) / 256, 256>>>(qkvp, cosp, sinp, q16, k16, v16);
    }
    // 3) attention (fp16 tensor cores) -> bf16 hi/lo directly
    attn_mma<<<dim3(T_TOK / 64, N_HEADS), 128, ATTN_SMEM>>>(q16, k16, v16, cu,
                                                            ath, atl);
    // 4) output projection (R4-proven GEMM)
    gemm_mma_split<false><<<dim3(D_MODEL / 128, T_TOK / 128), 256, GEMM_SMEM>>>(
        ath, atl, woh, wol, out, D_MODEL);
}

// round 13
// speedup vs baseline: 4.4983x; 2.2129x over previous
#include <cuda_runtime.h>
#include <cuda_bf16.h>
#include <cuda_fp16.h>
#include <math.h>
#include <stdint.h>

// ---------------- problem constants ----------------
#define T_TOK   2048
#define D_MODEL 4096
#define N_HEADS 32
#define KV_HEADS 8
#define HEAD_DIM 128
#define QKV_OUT 6144
#define CLIP_V  8.0f
#define GK      4096

// ---------------- scratch (device globals; no allocations) ----------------
__device__ float g_qkv[(size_t)T_TOK * QKV_OUT];

__device__ __half g_hid16[(size_t)T_TOK * D_MODEL];
__device__ __half g_wqkv16[(size_t)QKV_OUT * D_MODEL];
__device__ __half g_wo16[(size_t)D_MODEL * D_MODEL];
__device__ __half g_att16[(size_t)T_TOK * D_MODEL];

__device__ __half g_q16[(size_t)T_TOK * D_MODEL];
__device__ __half g_k16[(size_t)T_TOK * KV_HEADS * HEAD_DIM];
__device__ __half g_v16[(size_t)T_TOK * KV_HEADS * HEAD_DIM];

// ---------------- helpers ----------------
__device__ __forceinline__ uint32_t smem_u32(const void* p) {
    uint32_t a;
    asm("{ .reg .u64 t; cvta.to.shared.u64 t, %1; cvt.u32.u64 %0, t; }"
        : "=r"(a) : "l"(p));
    return a;
}
__device__ __forceinline__ void ldsm4(uint32_t addr, uint32_t* r) {
    asm volatile("ldmatrix.sync.aligned.m8n8.x4.shared.b16 {%0,%1,%2,%3}, [%4];"
                 : "=r"(r[0]), "=r"(r[1]), "=r"(r[2]), "=r"(r[3]) : "r"(addr));
}
__device__ __forceinline__ void ldsm4t(uint32_t addr, uint32_t* r) {
    asm volatile("ldmatrix.sync.aligned.m8n8.x4.trans.shared.b16 {%0,%1,%2,%3}, [%4];"
                 : "=r"(r[0]), "=r"(r[1]), "=r"(r[2]), "=r"(r[3]) : "r"(addr));
}
__device__ __forceinline__ void mma_fp16(float* d, const uint32_t* a,
                                         uint32_t b0, uint32_t b1) {
    asm volatile(
        "mma.sync.aligned.m16n8k16.row.col.f32.f16.f16.f32 "
        "{%0,%1,%2,%3}, {%4,%5,%6,%7}, {%8,%9}, {%0,%1,%2,%3};"
        : "+f"(d[0]), "+f"(d[1]), "+f"(d[2]), "+f"(d[3])
        : "r"(a[0]), "r"(a[1]), "r"(a[2]), "r"(a[3]), "r"(b0), "r"(b1));
}
__device__ __forceinline__ uint32_t pack_half2(float lo, float hi) {
    uint32_t u;
    asm("cvt.rn.f16x2.f32 %0, %1, %2;" : "=r"(u) : "f"(hi), "f"(lo));
    return u;
}

// ===================================================================
// Cast fp32 -> fp16 (vectorized)
// ===================================================================
__global__ __launch_bounds__(256) void cast_fp16(const float* __restrict__ x,
                                                 __half* __restrict__ y, int n4) {
    int i = blockIdx.x * blockDim.x + threadIdx.x;
    if (i >= n4) return;
    float4 f = ((const float4*)x)[i];
    __half h[4];
    h[0] = __float2half_rn(f.x);
    h[1] = __float2half_rn(f.y);
    h[2] = __float2half_rn(f.z);
    h[3] = __float2half_rn(f.w);
    ((uint2*)y)[i] = *(uint2*)h;
}

// ===================================================================
// fp16 single-product GEMM via mma.sync (R4-proven structure):
//   C[M,N] = A[M,K] @ B[N,K]^T, K=4096
// CTA 128x128, BK=32, 256 thr (8 warps 2x4), warp tile 64x32.
// smem rows padded to 40 halves (80B). Stage = A|B = 20480 B, 2 stages.
// ===================================================================
#define PADK       40
#define TILE_BY    (128 * PADK * 2)        // 10240 B per matrix tile
#define STAGE_BY   (2 * TILE_BY)           // A|B = 20480 B
#define GEMM_SMEM  (2 * STAGE_BY)          // 40960 B
#define KT_N       (GK / 32)               // 128

template <bool CLIP>
__global__ __launch_bounds__(256) void gemm_mma_fp16(
    const __half* __restrict__ A, const __half* __restrict__ B,
    float* __restrict__ C, int N) {
    extern __shared__ char dsm[];
    const uint32_t sb = smem_u32(dsm);

    const int tid = threadIdx.x;
    const int wid = tid >> 5, lane = tid & 31;
    const int warp_m = wid & 1, warp_n = wid >> 1;
    const int m0 = blockIdx.y * 128, n0 = blockIdx.x * 128;

    const __half* gsrc[2] = {A + (size_t)m0 * GK, B + (size_t)n0 * GK};

    // ldmatrix per-lane byte offsets (within a stage)
    const int g = lane >> 3, r = lane & 7;
    uint32_t a_off[4], b_off[2];
#pragma unroll
    for (int fm = 0; fm < 4; fm++)
        a_off[fm] = (uint32_t)((warp_m * 64 + fm * 16 + (g & 1) * 8 + r) * (PADK * 2)
                               + (g >> 1) * 16);
#pragma unroll
    for (int nf = 0; nf < 2; nf++)
        b_off[nf] = (uint32_t)((warp_n * 32 + nf * 16 + (g >> 1) * 8 + r) * (PADK * 2)
                               + (g & 1) * 16);

    float acc[4][4][4];
#pragma unroll
    for (int i = 0; i < 4; i++)
#pragma unroll
        for (int j = 0; j < 4; j++)
#pragma unroll
            for (int q = 0; q < 4; q++) acc[i][j][q] = 0.f;

    // cp.async prefetch of one BK=32 stage (A + B: 16384 B)
    auto prefetch = [&](int kt) {
        const uint32_t so = sb + (uint32_t)(kt & 1) * STAGE_BY;
        const int k0 = kt * 32;
#pragma unroll
        for (int it = 0; it < 4; it++) {
            int gi = tid + it * 256;
            int tile = gi >> 9;
            int w = gi & 511;
            int row = w >> 2, c = w & 3;
            const char* src = (const char*)(gsrc[tile] + (size_t)row * GK + k0 + c * 8);
            uint32_t dst = so + (uint32_t)(tile * TILE_BY + row * (PADK * 2) + c * 16);
            asm volatile("cp.async.cg.shared.global [%0], [%1], 16;"
                         :: "r"(dst), "l"(src));
        }
        asm volatile("cp.async.commit_group;");
    };

    prefetch(0);

    for (int kt = 0; kt < KT_N; kt++) {
        if (kt + 1 < KT_N) {
            prefetch(kt + 1);
            asm volatile("cp.async.wait_group 1;");
        } else {
            asm volatile("cp.async.wait_group 0;");
        }
        __syncthreads();

        const uint32_t so = sb + (uint32_t)(kt & 1) * STAGE_BY;
#pragma unroll
        for (int ks = 0; ks < 2; ks++) {
            const uint32_t ko = (uint32_t)(ks * 32);
            uint32_t Af[4][4], Bf[2][4];
#pragma unroll
            for (int fm = 0; fm < 4; fm++)
                ldsm4(so + a_off[fm] + ko, Af[fm]);
#pragma unroll
            for (int nf = 0; nf < 2; nf++)
                ldsm4(so + TILE_BY + b_off[nf] + ko, Bf[nf]);
#pragma unroll
            for (int fm = 0; fm < 4; fm++)
#pragma unroll
                for (int fn = 0; fn < 4; fn++) {
                    const int n2 = fn >> 1, j = (fn & 1) * 2;
                    mma_fp16(acc[fm][fn], Af[fm], Bf[n2][j], Bf[n2][j + 1]);
                }
        }
        __syncthreads();
    }

    // epilogue: direct fp32 stores (float2 per fragment row)
    const int mrow = m0 + warp_m * 64 + (lane >> 2);
    const int ncol = n0 + warp_n * 32 + (lane & 3) * 2;
#pragma unroll
    for (int fm = 0; fm < 4; fm++)
#pragma unroll
        for (int fn = 0; fn < 4; fn++) {
            float* p0 = C + (size_t)(mrow + fm * 16) * N + ncol + fn * 8;
            float* p1 = p0 + (size_t)8 * N;
            float2 v0 = {acc[fm][fn][0], acc[fm][fn][1]};
            float2 v1 = {acc[fm][fn][2], acc[fm][fn][3]};
            if (CLIP) {
                v0.x = fminf(fmaxf(v0.x, -CLIP_V), CLIP_V);
                v0.y = fminf(fmaxf(v0.y, -CLIP_V), CLIP_V);
                v1.x = fminf(fmaxf(v1.x, -CLIP_V), CLIP_V);
                v1.y = fminf(fmaxf(v1.y, -CLIP_V), CLIP_V);
            }
            *(float2*)p0 = v0;
            *(float2*)p1 = v1;
        }
}

// ===================================================================
// RoPE + fp16 cast: qkv fp32 -> q16 [T][4096], k16/v16 [T][1024]
// ===================================================================
#define ROPE_TOTAL1 (T_TOK * 40 * 64)
#define ROPE_TOTAL2 (T_TOK * 1024)

__global__ void rope_cast(const float* __restrict__ qkv,
                          const float* __restrict__ cosp,
                          const float* __restrict__ sinp,
                          __half* __restrict__ q16,
                          __half* __restrict__ k16,
                          __half* __restrict__ v16) {
    int idx = blockIdx.x * blockDim.x + threadIdx.x;
    if (idx < ROPE_TOTAL1) {
        int d  = idx & 63;
        int rr = idx >> 6;
        int hh = rr % 40;
        int t  = rr / 40;
        size_t base = (size_t)t * QKV_OUT + (hh < 32 ? hh * 128 : 4096 + (hh - 32) * 128);
        float x1 = qkv[base + d];
        float x2 = qkv[base + 64 + d];
        float c = cosp[t * 64 + d];
        float s = sinp[t * 64 + d];
        float o1 = x1 * c - x2 * s;
        float o2 = x2 * c + x1 * s;
        if (hh < 32) {
            size_t ob = (size_t)t * 4096 + hh * 128;
            q16[ob + d]      = __float2half_rn(o1);
            q16[ob + 64 + d] = __float2half_rn(o2);
        } else {
            size_t ob = (size_t)t * 1024 + (hh - 32) * 128;
            k16[ob + d]      = __float2half_rn(o1);
            k16[ob + 64 + d] = __float2half_rn(o2);
        }
    } else if (idx < ROPE_TOTAL1 + ROPE_TOTAL2) {
        int j = idx - ROPE_TOTAL1;
        int t = j >> 10, d = j & 1023;
        v16[j] = __float2half_rn(qkv[(size_t)t * QKV_OUT + 5120 + d]);
    }
}

// ===================================================================
// Flash attention, fp16 mma.sync, varlen causal, GQA (R11-proven).
// Epilogue writes fp16 directly (single stream).
// ===================================================================
#define APAD 136
#define ATTN_SMEM (3 * 64 * APAD * 2)   // Qs, Ks, Vs = 52224 B

__global__ __launch_bounds__(128) void attn_mma(
    const __half* __restrict__ Q, const __half* __restrict__ K,
    const __half* __restrict__ V, const int* __restrict__ cu,
    __half* __restrict__ att16) {
    extern __shared__ __half hsm[];
    __half* Qs = hsm;
    __half* Ks = Qs + 64 * APAD;
    __half* Vs = Ks + 64 * APAD;

    const int tid = threadIdx.x, w = tid >> 5, lane = tid & 31;
    const int g = lane >> 3, r = lane & 7;
    const int qt = blockIdx.x, h = blockIdx.y;
    const int q0 = qt * 64, kh = h >> 2;

    int seg_start = 0;
#pragma unroll
    for (int s = 1; s < 4; s++) {
        int c = cu[s];
        if (q0 >= c) seg_start = c;
    }

    // load Q tile (64 x 128 fp16)
#pragma unroll
    for (int it = 0; it < 8; it++) {
        int gi = tid + it * 128;
        int row = gi >> 4, c = gi & 15;
        *(uint4*)&Qs[row * APAD + c * 8] =
            *(const uint4*)&Q[(size_t)(q0 + row) * 4096 + h * 128 + c * 8];
    }

    const uint32_t q_off = smem_u32(Qs)
        + (uint32_t)(((w * 16 + (g & 1) * 8 + r) * APAD + (g >> 1) * 8) * 2);
    const uint32_t k_off = smem_u32(Ks)
        + (uint32_t)((((g >> 1) * 8 + r) * APAD + (g & 1) * 8) * 2);
    const uint32_t v_off = smem_u32(Vs)
        + (uint32_t)((((g & 1) * 8 + r) * APAD + (g >> 1) * 8) * 2);

    float Oa[16][4];
#pragma unroll
    for (int i = 0; i < 16; i++)
#pragma unroll
        for (int j = 0; j < 4; j++) Oa[i][j] = 0.f;
    float m0 = -1e30f, m1 = -1e30f, l0 = 0.f, l1 = 0.f;
    const int row0 = q0 + w * 16 + (lane >> 2), row1 = row0 + 8;
    const float sc = 0.08838834764831845f * 1.4426950408889634f;  // scale*log2e

    for (int kstart = seg_start; kstart < q0 + 64; kstart += 64) {
        __syncthreads();
#pragma unroll
        for (int it = 0; it < 8; it++) {
            int gi = tid + it * 128;
            int row = gi >> 4, c = gi & 15;
            size_t gb = (size_t)(kstart + row) * 1024 + kh * 128 + c * 8;
            *(uint4*)&Ks[row * APAD + c * 8] = *(const uint4*)&K[gb];
            *(uint4*)&Vs[row * APAD + c * 8] = *(const uint4*)&V[gb];
        }
        __syncthreads();

        // ---- S = Q K^T ----
        float Sa[8][4];
#pragma unroll
        for (int i = 0; i < 8; i++)
#pragma unroll
            for (int j = 0; j < 4; j++) Sa[i][j] = 0.f;
#pragma unroll
        for (int kstep = 0; kstep < 8; kstep++) {
            uint32_t qf[4];
            ldsm4(q_off + kstep * 32, qf);
#pragma unroll
            for (int nb16 = 0; nb16 < 4; nb16++) {
                uint32_t kf[4];
                ldsm4(k_off + nb16 * (16 * APAD * 2) + kstep * 32, kf);
                mma_fp16(Sa[2 * nb16], qf, kf[0], kf[1]);
                mma_fp16(Sa[2 * nb16 + 1], qf, kf[2], kf[3]);
            }
        }

        // scale to log2 domain + causal mask (only last tile)
#pragma unroll
        for (int nb = 0; nb < 8; nb++)
#pragma unroll
            for (int e = 0; e < 4; e++) Sa[nb][e] *= sc;
        if (kstart == q0) {
#pragma unroll
            for (int nb = 0; nb < 8; nb++) {
                int cg = kstart + nb * 8 + 2 * (lane & 3);
                if (cg > row0)     Sa[nb][0] = -1e30f;
                if (cg + 1 > row0) Sa[nb][1] = -1e30f;
                if (cg > row1)     Sa[nb][2] = -1e30f;
                if (cg + 1 > row1) Sa[nb][3] = -1e30f;
            }
        }

        // ---- online softmax ----
        float mx0 = -1e30f, mx1 = -1e30f;
#pragma unroll
        for (int nb = 0; nb < 8; nb++) {
            mx0 = fmaxf(mx0, fmaxf(Sa[nb][0], Sa[nb][1]));
            mx1 = fmaxf(mx1, fmaxf(Sa[nb][2], Sa[nb][3]));
        }
        mx0 = fmaxf(mx0, __shfl_xor_sync(0xffffffffu, mx0, 1));
        mx0 = fmaxf(mx0, __shfl_xor_sync(0xffffffffu, mx0, 2));
        mx1 = fmaxf(mx1, __shfl_xor_sync(0xffffffffu, mx1, 1));
        mx1 = fmaxf(mx1, __shfl_xor_sync(0xffffffffu, mx1, 2));
        float mn0 = fmaxf(m0, mx0), mn1 = fmaxf(m1, mx1);
        float c0 = exp2f(m0 - mn0), c1 = exp2f(m1 - mn1);
        m0 = mn0;
        m1 = mn1;
        float s0 = 0.f, s1 = 0.f;
        uint32_t pA[8], pB[8];
#pragma unroll
        for (int nb = 0; nb < 8; nb++) {
            float p0 = exp2f(Sa[nb][0] - mn0);
            float p1 = exp2f(Sa[nb][1] - mn0);
            float p2 = exp2f(Sa[nb][2] - mn1);
            float p3 = exp2f(Sa[nb][3] - mn1);
            s0 += p0 + p1;
            s1 += p2 + p3;
            pA[nb] = pack_half2(p0, p1);
            pB[nb] = pack_half2(p2, p3);
        }
        s0 += __shfl_xor_sync(0xffffffffu, s0, 1);
        s0 += __shfl_xor_sync(0xffffffffu, s0, 2);
        s1 += __shfl_xor_sync(0xffffffffu, s1, 1);
        s1 += __shfl_xor_sync(0xffffffffu, s1, 2);
        l0 = l0 * c0 + s0;
        l1 = l1 * c1 + s1;
#pragma unroll
        for (int db = 0; db < 16; db++) {
            Oa[db][0] *= c0;
            Oa[db][1] *= c0;
            Oa[db][2] *= c1;
            Oa[db][3] *= c1;
        }

        // ---- O += P V ----
#pragma unroll
        for (int ks2 = 0; ks2 < 4; ks2++) {
            uint32_t af[4] = {pA[2 * ks2], pB[2 * ks2],
                              pA[2 * ks2 + 1], pB[2 * ks2 + 1]};
#pragma unroll
            for (int db16 = 0; db16 < 8; db16++) {
                uint32_t vf[4];
                ldsm4t(v_off + ks2 * (16 * APAD * 2) + db16 * 32, vf);
                mma_fp16(Oa[2 * db16], af, vf[0], vf[1]);
                mma_fp16(Oa[2 * db16 + 1], af, vf[2], vf[3]);
            }
        }
    }

    // epilogue: normalize, write fp16 directly
    float i0 = 1.f / l0, i1 = 1.f / l1;
#pragma unroll
    for (int db = 0; db < 16; db++) {
        int col = h * 128 + db * 8 + (lane & 3) * 2;
        float x0 = Oa[db][0] * i0, x1 = Oa[db][1] * i0;
        float x2 = Oa[db][2] * i1, x3 = Oa[db][3] * i1;
        *(uint32_t*)&att16[(size_t)row0 * 4096 + col] = pack_half2(x0, x1);
        *(uint32_t*)&att16[(size_t)row1 * 4096 + col] = pack_half2(x2, x3);
    }
}

// ===================================================================
// launch
// ===================================================================
extern "C" void kernel_launch(void* const* d_in, const int* in_sizes, int n_in,
                              void* d_out, int out_size) {
    const float* hidden = (const float*)d_in[0];
    const float* w_qkv  = (const float*)d_in[1];
    const float* w_o    = (const float*)d_in[2];
    const float* cosp   = (const float*)d_in[3];
    const float* sinp   = (const float*)d_in[4];
    const int*   cu     = (const int*)d_in[5];
    float* out = (float*)d_out;

    float* qkvp;
    __half *h16, *wq16, *wo16, *at16, *q16, *k16, *v16;
    cudaGetSymbolAddress((void**)&qkvp, g_qkv);
    cudaGetSymbolAddress((void**)&h16,  g_hid16);
    cudaGetSymbolAddress((void**)&wq16, g_wqkv16);
    cudaGetSymbolAddress((void**)&wo16, g_wo16);
    cudaGetSymbolAddress((void**)&at16, g_att16);
    cudaGetSymbolAddress((void**)&q16,  g_q16);
    cudaGetSymbolAddress((void**)&k16,  g_k16);
    cudaGetSymbolAddress((void**)&v16,  g_v16);

    cudaFuncSetAttribute(gemm_mma_fp16<true>,
                         cudaFuncAttributeMaxDynamicSharedMemorySize, GEMM_SMEM);
    cudaFuncSetAttribute(gemm_mma_fp16<false>,
                         cudaFuncAttributeMaxDynamicSharedMemorySize, GEMM_SMEM);
    cudaFuncSetAttribute(attn_mma,
                         cudaFuncAttributeMaxDynamicSharedMemorySize, ATTN_SMEM);

    // 0) cast inputs/weights to fp16
    {
        int n4;
        n4 = T_TOK * D_MODEL / 4;
        cast_fp16<<<(n4 + 255) / 256, 256>>>(hidden, h16, n4);
        n4 = QKV_OUT * D_MODEL / 4;
        cast_fp16<<<(n4 + 255) / 256, 256>>>(w_qkv, wq16, n4);
        n4 = D_MODEL * D_MODEL / 4;
        cast_fp16<<<(n4 + 255) / 256, 256>>>(w_o, wo16, n4);
    }
    // 1) QKV projection + clip (fp16 single-product)
    gemm_mma_fp16<true><<<dim3(QKV_OUT / 128, T_TOK / 128), 256, GEMM_SMEM>>>(
        h16, wq16, qkvp, QKV_OUT);
    // 2) RoPE + fp16 cast
    {
        int total = ROPE_TOTAL1 + ROPE_TOTAL2;
        rope_cast<<<(total + 255) / 256, 256>>>(qkvp, cosp, sinp, q16, k16, v16);
    }
    // 3) attention (fp16 tensor cores) -> fp16 directly
    attn_mma<<<dim3(T_TOK / 64, N_HEADS), 128, ATTN_SMEM>>>(q16, k16, v16, cu, at16);
    // 4) output projection (fp16 single-product)
    gemm_mma_fp16<false><<<dim3(D_MODEL / 128, T_TOK / 128), 256, GEMM_SMEM>>>(
        at16, wo16, out, D_MODEL);
}

// round 14
// speedup vs baseline: 5.0290x; 1.1180x over previous
#include <cuda_runtime.h>
#include <cuda_bf16.h>
#include <cuda_fp16.h>
#include <math.h>
#include <stdint.h>

// ---------------- problem constants ----------------
#define T_TOK   2048
#define D_MODEL 4096
#define N_HEADS 32
#define KV_HEADS 8
#define HEAD_DIM 128
#define QKV_OUT 6144
#define CLIP_V  8.0f
#define GK      4096

// ---------------- scratch (device globals; no allocations) ----------------
__device__ float g_qkv[(size_t)T_TOK * QKV_OUT];

__device__ __half g_hid16[(size_t)T_TOK * D_MODEL];
__device__ __half g_wqkv16[(size_t)QKV_OUT * D_MODEL];
__device__ __half g_wo16[(size_t)D_MODEL * D_MODEL];
__device__ __half g_att16[(size_t)T_TOK * D_MODEL];

__device__ __half g_q16[(size_t)T_TOK * D_MODEL];
__device__ __half g_k16[(size_t)T_TOK * KV_HEADS * HEAD_DIM];
__device__ __half g_v16[(size_t)T_TOK * KV_HEADS * HEAD_DIM];

// ---------------- helpers ----------------
__device__ __forceinline__ uint32_t smem_u32(const void* p) {
    uint32_t a;
    asm("{ .reg .u64 t; cvta.to.shared.u64 t, %1; cvt.u32.u64 %0, t; }"
        : "=r"(a) : "l"(p));
    return a;
}
__device__ __forceinline__ void ldsm4(uint32_t addr, uint32_t* r) {
    asm volatile("ldmatrix.sync.aligned.m8n8.x4.shared.b16 {%0,%1,%2,%3}, [%4];"
                 : "=r"(r[0]), "=r"(r[1]), "=r"(r[2]), "=r"(r[3]) : "r"(addr));
}
__device__ __forceinline__ void ldsm4t(uint32_t addr, uint32_t* r) {
    asm volatile("ldmatrix.sync.aligned.m8n8.x4.trans.shared.b16 {%0,%1,%2,%3}, [%4];"
                 : "=r"(r[0]), "=r"(r[1]), "=r"(r[2]), "=r"(r[3]) : "r"(addr));
}
__device__ __forceinline__ void mma_fp16(float* d, const uint32_t* a,
                                         uint32_t b0, uint32_t b1) {
    asm volatile(
        "mma.sync.aligned.m16n8k16.row.col.f32.f16.f16.f32 "
        "{%0,%1,%2,%3}, {%4,%5,%6,%7}, {%8,%9}, {%0,%1,%2,%3};"
        : "+f"(d[0]), "+f"(d[1]), "+f"(d[2]), "+f"(d[3])
        : "r"(a[0]), "r"(a[1]), "r"(a[2]), "r"(a[3]), "r"(b0), "r"(b1));
}
__device__ __forceinline__ uint32_t pack_half2(float lo, float hi) {
    uint32_t u;
    asm("cvt.rn.f16x2.f32 %0, %1, %2;" : "=r"(u) : "f"(hi), "f"(lo));
    return u;
}

// ===================================================================
// Cast fp32 -> fp16 (vectorized)
// ===================================================================
__global__ __launch_bounds__(256) void cast_fp16(const float* __restrict__ x,
                                                 __half* __restrict__ y, int n4) {
    int i = blockIdx.x * blockDim.x + threadIdx.x;
    if (i >= n4) return;
    float4 f = ((const float4*)x)[i];
    __half h[4];
    h[0] = __float2half_rn(f.x);
    h[1] = __float2half_rn(f.y);
    h[2] = __float2half_rn(f.z);
    h[3] = __float2half_rn(f.w);
    ((uint2*)y)[i] = *(uint2*)h;
}

// ===================================================================
// fp16 single-product GEMM via mma.sync, 3-stage cp.async pipeline:
//   C[M,N] = A[M,K] @ B[N,K]^T, K=4096
// CTA 128x128, BK=32, 256 thr (8 warps 2x4), warp tile 64x32.
// smem rows padded to 40 halves (80B). Stage = A|B = 20480 B, 3 stages
// = 61440 B -> still 2 CTAs/SM (register-bound), 1 syncthreads per kt.
// ===================================================================
#define PADK       40
#define TILE_BY    (128 * PADK * 2)        // 10240 B per matrix tile
#define STAGE_BY   (2 * TILE_BY)           // A|B = 20480 B
#define GEMM_SMEM  (3 * STAGE_BY)          // 61440 B
#define KT_N       (GK / 32)               // 128

template <bool CLIP>
__global__ __launch_bounds__(256) void gemm_mma_fp16(
    const __half* __restrict__ A, const __half* __restrict__ B,
    float* __restrict__ C, int N) {
    extern __shared__ char dsm[];
    const uint32_t sb = smem_u32(dsm);

    const int tid = threadIdx.x;
    const int wid = tid >> 5, lane = tid & 31;
    const int warp_m = wid & 1, warp_n = wid >> 1;
    const int m0 = blockIdx.y * 128, n0 = blockIdx.x * 128;

    const __half* gsrc[2] = {A + (size_t)m0 * GK, B + (size_t)n0 * GK};

    // ldmatrix per-lane byte offsets (within a stage)
    const int g = lane >> 3, r = lane & 7;
    uint32_t a_off[4], b_off[2];
#pragma unroll
    for (int fm = 0; fm < 4; fm++)
        a_off[fm] = (uint32_t)((warp_m * 64 + fm * 16 + (g & 1) * 8 + r) * (PADK * 2)
                               + (g >> 1) * 16);
#pragma unroll
    for (int nf = 0; nf < 2; nf++)
        b_off[nf] = (uint32_t)((warp_n * 32 + nf * 16 + (g >> 1) * 8 + r) * (PADK * 2)
                               + (g & 1) * 16);

    float acc[4][4][4];
#pragma unroll
    for (int i = 0; i < 4; i++)
#pragma unroll
        for (int j = 0; j < 4; j++)
#pragma unroll
            for (int q = 0; q < 4; q++) acc[i][j][q] = 0.f;

    // cp.async prefetch of one BK=32 stage (A + B: 16384 B)
    auto prefetch = [&](int stage, int kt) {
        const uint32_t so = sb + (uint32_t)stage * STAGE_BY;
        const int k0 = kt * 32;
#pragma unroll
        for (int it = 0; it < 4; it++) {
            int gi = tid + it * 256;
            int tile = gi >> 9;
            int w = gi & 511;
            int row = w >> 2, c = w & 3;
            const char* src = (const char*)(gsrc[tile] + (size_t)row * GK + k0 + c * 8);
            uint32_t dst = so + (uint32_t)(tile * TILE_BY + row * (PADK * 2) + c * 16);
            asm volatile("cp.async.cg.shared.global [%0], [%1], 16;"
                         :: "r"(dst), "l"(src));
        }
        asm volatile("cp.async.commit_group;");
    };

    prefetch(0, 0);
    prefetch(1, 1);
    asm volatile("cp.async.wait_group 1;");
    __syncthreads();

    int st = 0, pst = 2;
    for (int kt = 0; kt < KT_N; kt++) {
        if (kt + 2 < KT_N) prefetch(pst, kt + 2);

        const uint32_t so = sb + (uint32_t)st * STAGE_BY;
#pragma unroll
        for (int ks = 0; ks < 2; ks++) {
            const uint32_t ko = (uint32_t)(ks * 32);
            uint32_t Af[4][4], Bf[2][4];
#pragma unroll
            for (int fm = 0; fm < 4; fm++)
                ldsm4(so + a_off[fm] + ko, Af[fm]);
#pragma unroll
            for (int nf = 0; nf < 2; nf++)
                ldsm4(so + TILE_BY + b_off[nf] + ko, Bf[nf]);
#pragma unroll
            for (int fm = 0; fm < 4; fm++)
#pragma unroll
                for (int fn = 0; fn < 4; fn++) {
                    const int n2 = fn >> 1, j = (fn & 1) * 2;
                    mma_fp16(acc[fm][fn], Af[fm], Bf[n2][j], Bf[n2][j + 1]);
                }
        }

        if (kt + 1 < KT_N) {
            if (kt + 2 < KT_N) {
                asm volatile("cp.async.wait_group 1;");
            } else {
                asm volatile("cp.async.wait_group 0;");
            }
            __syncthreads();
        }
        st = (st == 2) ? 0 : st + 1;
        pst = (pst == 2) ? 0 : pst + 1;
    }

    // epilogue: direct fp32 stores (float2 per fragment row)
    const int mrow = m0 + warp_m * 64 + (lane >> 2);
    const int ncol = n0 + warp_n * 32 + (lane & 3) * 2;
#pragma unroll
    for (int fm = 0; fm < 4; fm++)
#pragma unroll
        for (int fn = 0; fn < 4; fn++) {
            float* p0 = C + (size_t)(mrow + fm * 16) * N + ncol + fn * 8;
            float* p1 = p0 + (size_t)8 * N;
            float2 v0 = {acc[fm][fn][0], acc[fm][fn][1]};
            float2 v1 = {acc[fm][fn][2], acc[fm][fn][3]};
            if (CLIP) {
                v0.x = fminf(fmaxf(v0.x, -CLIP_V), CLIP_V);
                v0.y = fminf(fmaxf(v0.y, -CLIP_V), CLIP_V);
                v1.x = fminf(fmaxf(v1.x, -CLIP_V), CLIP_V);
                v1.y = fminf(fmaxf(v1.y, -CLIP_V), CLIP_V);
            }
            *(float2*)p0 = v0;
            *(float2*)p1 = v1;
        }
}

// ===================================================================
// RoPE + fp16 cast: qkv fp32 -> q16 [T][4096], k16/v16 [T][1024]
// ===================================================================
#define ROPE_TOTAL1 (T_TOK * 40 * 64)
#define ROPE_TOTAL2 (T_TOK * 1024)

__global__ void rope_cast(const float* __restrict__ qkv,
                          const float* __restrict__ cosp,
                          const float* __restrict__ sinp,
                          __half* __restrict__ q16,
                          __half* __restrict__ k16,
                          __half* __restrict__ v16) {
    int idx = blockIdx.x * blockDim.x + threadIdx.x;
    if (idx < ROPE_TOTAL1) {
        int d  = idx & 63;
        int rr = idx >> 6;
        int hh = rr % 40;
        int t  = rr / 40;
        size_t base = (size_t)t * QKV_OUT + (hh < 32 ? hh * 128 : 4096 + (hh - 32) * 128);
        float x1 = qkv[base + d];
        float x2 = qkv[base + 64 + d];
        float c = cosp[t * 64 + d];
        float s = sinp[t * 64 + d];
        float o1 = x1 * c - x2 * s;
        float o2 = x2 * c + x1 * s;
        if (hh < 32) {
            size_t ob = (size_t)t * 4096 + hh * 128;
            q16[ob + d]      = __float2half_rn(o1);
            q16[ob + 64 + d] = __float2half_rn(o2);
        } else {
            size_t ob = (size_t)t * 1024 + (hh - 32) * 128;
            k16[ob + d]      = __float2half_rn(o1);
            k16[ob + 64 + d] = __float2half_rn(o2);
        }
    } else if (idx < ROPE_TOTAL1 + ROPE_TOTAL2) {
        int j = idx - ROPE_TOTAL1;
        int t = j >> 10, d = j & 1023;
        v16[j] = __float2half_rn(qkv[(size_t)t * QKV_OUT + 5120 + d]);
    }
}

// ===================================================================
// Flash attention, fp16 mma.sync, varlen causal, GQA (R13-proven).
// ===================================================================
#define APAD 136
#define ATTN_SMEM (3 * 64 * APAD * 2)   // Qs, Ks, Vs = 52224 B

__global__ __launch_bounds__(128) void attn_mma(
    const __half* __restrict__ Q, const __half* __restrict__ K,
    const __half* __restrict__ V, const int* __restrict__ cu,
    __half* __restrict__ att16) {
    extern __shared__ __half hsm[];
    __half* Qs = hsm;
    __half* Ks = Qs + 64 * APAD;
    __half* Vs = Ks + 64 * APAD;

    const int tid = threadIdx.x, w = tid >> 5, lane = tid & 31;
    const int g = lane >> 3, r = lane & 7;
    const int qt = blockIdx.x, h = blockIdx.y;
    const int q0 = qt * 64, kh = h >> 2;

    int seg_start = 0;
#pragma unroll
    for (int s = 1; s < 4; s++) {
        int c = cu[s];
        if (q0 >= c) seg_start = c;
    }

    // load Q tile (64 x 128 fp16)
#pragma unroll
    for (int it = 0; it < 8; it++) {
        int gi = tid + it * 128;
        int row = gi >> 4, c = gi & 15;
        *(uint4*)&Qs[row * APAD + c * 8] =
            *(const uint4*)&Q[(size_t)(q0 + row) * 4096 + h * 128 + c * 8];
    }

    const uint32_t q_off = smem_u32(Qs)
        + (uint32_t)(((w * 16 + (g & 1) * 8 + r) * APAD + (g >> 1) * 8) * 2);
    const uint32_t k_off = smem_u32(Ks)
        + (uint32_t)((((g >> 1) * 8 + r) * APAD + (g & 1) * 8) * 2);
    const uint32_t v_off = smem_u32(Vs)
        + (uint32_t)((((g & 1) * 8 + r) * APAD + (g >> 1) * 8) * 2);

    float Oa[16][4];
#pragma unroll
    for (int i = 0; i < 16; i++)
#pragma unroll
        for (int j = 0; j < 4; j++) Oa[i][j] = 0.f;
    float m0 = -1e30f, m1 = -1e30f, l0 = 0.f, l1 = 0.f;
    const int row0 = q0 + w * 16 + (lane >> 2), row1 = row0 + 8;
    const float sc = 0.08838834764831845f * 1.4426950408889634f;  // scale*log2e

    for (int kstart = seg_start; kstart < q0 + 64; kstart += 64) {
        __syncthreads();
#pragma unroll
        for (int it = 0; it < 8; it++) {
            int gi = tid + it * 128;
            int row = gi >> 4, c = gi & 15;
            size_t gb = (size_t)(kstart + row) * 1024 + kh * 128 + c * 8;
            *(uint4*)&Ks[row * APAD + c * 8] = *(const uint4*)&K[gb];
            *(uint4*)&Vs[row * APAD + c * 8] = *(const uint4*)&V[gb];
        }
        __syncthreads();

        // ---- S = Q K^T ----
        float Sa[8][4];
#pragma unroll
        for (int i = 0; i < 8; i++)
#pragma unroll
            for (int j = 0; j < 4; j++) Sa[i][j] = 0.f;
#pragma unroll
        for (int kstep = 0; kstep < 8; kstep++) {
            uint32_t qf[4];
            ldsm4(q_off + kstep * 32, qf);
#pragma unroll
            for (int nb16 = 0; nb16 < 4; nb16++) {
                uint32_t kf[4];
                ldsm4(k_off + nb16 * (16 * APAD * 2) + kstep * 32, kf);
                mma_fp16(Sa[2 * nb16], qf, kf[0], kf[1]);
                mma_fp16(Sa[2 * nb16 + 1], qf, kf[2], kf[3]);
            }
        }

        // scale to log2 domain + causal mask (only last tile)
#pragma unroll
        for (int nb = 0; nb < 8; nb++)
#pragma unroll
            for (int e = 0; e < 4; e++) Sa[nb][e] *= sc;
        if (kstart == q0) {
#pragma unroll
            for (int nb = 0; nb < 8; nb++) {
                int cg = kstart + nb * 8 + 2 * (lane & 3);
                if (cg > row0)     Sa[nb][0] = -1e30f;
                if (cg + 1 > row0) Sa[nb][1] = -1e30f;
                if (cg > row1)     Sa[nb][2] = -1e30f;
                if (cg + 1 > row1) Sa[nb][3] = -1e30f;
            }
        }

        // ---- online softmax ----
        float mx0 = -1e30f, mx1 = -1e30f;
#pragma unroll
        for (int nb = 0; nb < 8; nb++) {
            mx0 = fmaxf(mx0, fmaxf(Sa[nb][0], Sa[nb][1]));
            mx1 = fmaxf(mx1, fmaxf(Sa[nb][2], Sa[nb][3]));
        }
        mx0 = fmaxf(mx0, __shfl_xor_sync(0xffffffffu, mx0, 1));
        mx0 = fmaxf(mx0, __shfl_xor_sync(0xffffffffu, mx0, 2));
        mx1 = fmaxf(mx1, __shfl_xor_sync(0xffffffffu, mx1, 1));
        mx1 = fmaxf(mx1, __shfl_xor_sync(0xffffffffu, mx1, 2));
        float mn0 = fmaxf(m0, mx0), mn1 = fmaxf(m1, mx1);
        float c0 = exp2f(m0 - mn0), c1 = exp2f(m1 - mn1);
        m0 = mn0;
        m1 = mn1;
        float s0 = 0.f, s1 = 0.f;
        uint32_t pA[8], pB[8];
#pragma unroll
        for (int nb = 0; nb < 8; nb++) {
            float p0 = exp2f(Sa[nb][0] - mn0);
            float p1 = exp2f(Sa[nb][1] - mn0);
            float p2 = exp2f(Sa[nb][2] - mn1);
            float p3 = exp2f(Sa[nb][3] - mn1);
            s0 += p0 + p1;
            s1 += p2 + p3;
            pA[nb] = pack_half2(p0, p1);
            pB[nb] = pack_half2(p2, p3);
        }
        s0 += __shfl_xor_sync(0xffffffffu, s0, 1);
        s0 += __shfl_xor_sync(0xffffffffu, s0, 2);
        s1 += __shfl_xor_sync(0xffffffffu, s1, 1);
        s1 += __shfl_xor_sync(0xffffffffu, s1, 2);
        l0 = l0 * c0 + s0;
        l1 = l1 * c1 + s1;
#pragma unroll
        for (int db = 0; db < 16; db++) {
            Oa[db][0] *= c0;
            Oa[db][1] *= c0;
            Oa[db][2] *= c1;
            Oa[db][3] *= c1;
        }

        // ---- O += P V ----
#pragma unroll
        for (int ks2 = 0; ks2 < 4; ks2++) {
            uint32_t af[4] = {pA[2 * ks2], pB[2 * ks2],
                              pA[2 * ks2 + 1], pB[2 * ks2 + 1]};
#pragma unroll
            for (int db16 = 0; db16 < 8; db16++) {
                uint32_t vf[4];
                ldsm4t(v_off + ks2 * (16 * APAD * 2) + db16 * 32, vf);
                mma_fp16(Oa[2 * db16], af, vf[0], vf[1]);
                mma_fp16(Oa[2 * db16 + 1], af, vf[2], vf[3]);
            }
        }
    }

    // epilogue: normalize, write fp16 directly
    float i0 = 1.f / l0, i1 = 1.f / l1;
#pragma unroll
    for (int db = 0; db < 16; db++) {
        int col = h * 128 + db * 8 + (lane & 3) * 2;
        float x0 = Oa[db][0] * i0, x1 = Oa[db][1] * i0;
        float x2 = Oa[db][2] * i1, x3 = Oa[db][3] * i1;
        *(uint32_t*)&att16[(size_t)row0 * 4096 + col] = pack_half2(x0, x1);
        *(uint32_t*)&att16[(size_t)row1 * 4096 + col] = pack_half2(x2, x3);
    }
}

// ===================================================================
// launch
// ===================================================================
extern "C" void kernel_launch(void* const* d_in, const int* in_sizes, int n_in,
                              void* d_out, int out_size) {
    const float* hidden = (const float*)d_in[0];
    const float* w_qkv  = (const float*)d_in[1];
    const float* w_o    = (const float*)d_in[2];
    const float* cosp   = (const float*)d_in[3];
    const float* sinp   = (const float*)d_in[4];
    const int*   cu     = (const int*)d_in[5];
    float* out = (float*)d_out;

    float* qkvp;
    __half *h16, *wq16, *wo16, *at16, *q16, *k16, *v16;
    cudaGetSymbolAddress((void**)&qkvp, g_qkv);
    cudaGetSymbolAddress((void**)&h16,  g_hid16);
    cudaGetSymbolAddress((void**)&wq16, g_wqkv16);
    cudaGetSymbolAddress((void**)&wo16, g_wo16);
    cudaGetSymbolAddress((void**)&at16, g_att16);
    cudaGetSymbolAddress((void**)&q16,  g_q16);
    cudaGetSymbolAddress((void**)&k16,  g_k16);
    cudaGetSymbolAddress((void**)&v16,  g_v16);

    cudaFuncSetAttribute(gemm_mma_fp16<true>,
                         cudaFuncAttributeMaxDynamicSharedMemorySize, GEMM_SMEM);
    cudaFuncSetAttribute(gemm_mma_fp16<false>,
                         cudaFuncAttributeMaxDynamicSharedMemorySize, GEMM_SMEM);
    cudaFuncSetAttribute(attn_mma,
                         cudaFuncAttributeMaxDynamicSharedMemorySize, ATTN_SMEM);

    // 0) cast inputs/weights to fp16
    {
        int n4;
        n4 = T_TOK * D_MODEL / 4;
        cast_fp16<<<(n4 + 255) / 256, 256>>>(hidden, h16, n4);
        n4 = QKV_OUT * D_MODEL / 4;
        cast_fp16<<<(n4 + 255) / 256, 256>>>(w_qkv, wq16, n4);
        n4 = D_MODEL * D_MODEL / 4;
        cast_fp16<<<(n4 + 255) / 256, 256>>>(w_o, wo16, n4);
    }
    // 1) QKV projection + clip (fp16 single-product, 3-stage)
    gemm_mma_fp16<true><<<dim3(QKV_OUT / 128, T_TOK / 128), 256, GEMM_SMEM>>>(
        h16, wq16, qkvp, QKV_OUT);
    // 2) RoPE + fp16 cast
    {
        int total = ROPE_TOTAL1 + ROPE_TOTAL2;
        rope_cast<<<(total + 255) / 256, 256>>>(qkvp, cosp, sinp, q16, k16, v16);
    }
    // 3) attention (fp16 tensor cores) -> fp16 directly
    attn_mma<<<dim3(T_TOK / 64, N_HEADS), 128, ATTN_SMEM>>>(q16, k16, v16, cu, at16);
    // 4) output projection (fp16 single-product, 3-stage)
    gemm_mma_fp16<false><<<dim3(D_MODEL / 128, T_TOK / 128), 256, GEMM_SMEM>>>(
        at16, wo16, out, D_MODEL);
}

// round 16
// speedup vs baseline: 5.3958x; 1.0729x over previous
#include <cuda_runtime.h>
#include <cuda_bf16.h>
#include <cuda_fp16.h>
#include <math.h>
#include <stdint.h>

// ---------------- problem constants ----------------
#define T_TOK   2048
#define D_MODEL 4096
#define N_HEADS 32
#define KV_HEADS 8
#define HEAD_DIM 128
#define QKV_OUT 6144
#define CLIP_V  8.0f
#define GK      4096

// ---------------- scratch (device globals; no allocations) ----------------
__device__ float g_qkv[(size_t)T_TOK * QKV_OUT];

__device__ __half g_hid16[(size_t)T_TOK * D_MODEL];
__device__ __half g_wqkv16[(size_t)QKV_OUT * D_MODEL];
__device__ __half g_wo16[(size_t)D_MODEL * D_MODEL];
__device__ __half g_att16[(size_t)T_TOK * D_MODEL];

__device__ __half g_q16[(size_t)T_TOK * D_MODEL];
__device__ __half g_k16[(size_t)T_TOK * KV_HEADS * HEAD_DIM];
__device__ __half g_v16[(size_t)T_TOK * KV_HEADS * HEAD_DIM];

// ---------------- helpers ----------------
__device__ __forceinline__ uint32_t smem_u32(const void* p) {
    uint32_t a;
    asm("{ .reg .u64 t; cvta.to.shared.u64 t, %1; cvt.u32.u64 %0, t; }"
        : "=r"(a) : "l"(p));
    return a;
}
__device__ __forceinline__ void ldsm4(uint32_t addr, uint32_t* r) {
    asm volatile("ldmatrix.sync.aligned.m8n8.x4.shared.b16 {%0,%1,%2,%3}, [%4];"
                 : "=r"(r[0]), "=r"(r[1]), "=r"(r[2]), "=r"(r[3]) : "r"(addr));
}
__device__ __forceinline__ void ldsm4t(uint32_t addr, uint32_t* r) {
    asm volatile("ldmatrix.sync.aligned.m8n8.x4.trans.shared.b16 {%0,%1,%2,%3}, [%4];"
                 : "=r"(r[0]), "=r"(r[1]), "=r"(r[2]), "=r"(r[3]) : "r"(addr));
}
__device__ __forceinline__ void mma_fp16(float* d, const uint32_t* a,
                                         uint32_t b0, uint32_t b1) {
    asm volatile(
        "mma.sync.aligned.m16n8k16.row.col.f32.f16.f16.f32 "
        "{%0,%1,%2,%3}, {%4,%5,%6,%7}, {%8,%9}, {%0,%1,%2,%3};"
        : "+f"(d[0]), "+f"(d[1]), "+f"(d[2]), "+f"(d[3])
        : "r"(a[0]), "r"(a[1]), "r"(a[2]), "r"(a[3]), "r"(b0), "r"(b1));
}
__device__ __forceinline__ uint32_t pack_half2(float lo, float hi) {
    uint32_t u;
    asm("cvt.rn.f16x2.f32 %0, %1, %2;" : "=r"(u) : "f"(hi), "f"(lo));
    return u;
}

// ===================================================================
// Cast fp32 -> fp16 (vectorized)
// ===================================================================
__global__ __launch_bounds__(256) void cast_fp16(const float* __restrict__ x,
                                                 __half* __restrict__ y, int n4) {
    int i = blockIdx.x * blockDim.x + threadIdx.x;
    if (i >= n4) return;
    float4 f = ((const float4*)x)[i];
    __half h[4];
    h[0] = __float2half_rn(f.x);
    h[1] = __float2half_rn(f.y);
    h[2] = __float2half_rn(f.z);
    h[3] = __float2half_rn(f.w);
    ((uint2*)y)[i] = *(uint2*)h;
}

// ===================================================================
// fp16 single-product GEMM via mma.sync, 3-stage cp.async pipeline:
//   C[M,N] = A[M,K] @ B[N,K]^T, K=4096
// CTA 128x128, BK=32, 128 thr (4 warps 2x2), warp tile 64x64.
// Per k16 step: 8 ldmatrix.x4 -> 32 HMMAs (128 B/MMA operand traffic).
// smem rows padded to 40 halves (80B). Stage = A|B = 20480 B, 3 stages
// = 61440 B; ~190 regs/thread -> 2 CTAs/SM (8 warps).
// ===================================================================
#define PADK       40
#define TILE_BY    (128 * PADK * 2)        // 10240 B per matrix tile
#define STAGE_BY   (2 * TILE_BY)           // A|B = 20480 B
#define GEMM_SMEM  (3 * STAGE_BY)          // 61440 B
#define KT_N       (GK / 32)               // 128

template <bool CLIP>
__global__ __launch_bounds__(128) void gemm_mma_fp16(
    const __half* __restrict__ A, const __half* __restrict__ B,
    float* __restrict__ C, int N) {
    extern __shared__ char dsm[];
    const uint32_t sb = smem_u32(dsm);

    const int tid = threadIdx.x;
    const int wid = tid >> 5, lane = tid & 31;
    const int warp_m = wid & 1, warp_n = wid >> 1;   // 2x2
    const int m0 = blockIdx.y * 128, n0 = blockIdx.x * 128;

    const __half* gsrc[2] = {A + (size_t)m0 * GK, B + (size_t)n0 * GK};

    // ldmatrix per-lane byte offsets (within a stage)
    const int g = lane >> 3, r = lane & 7;
    uint32_t a_off[4], b_off[4];
#pragma unroll
    for (int fm = 0; fm < 4; fm++)
        a_off[fm] = (uint32_t)((warp_m * 64 + fm * 16 + (g & 1) * 8 + r) * (PADK * 2)
                               + (g >> 1) * 16);
#pragma unroll
    for (int nf = 0; nf < 4; nf++)
        b_off[nf] = (uint32_t)((warp_n * 64 + nf * 16 + (g >> 1) * 8 + r) * (PADK * 2)
                               + (g & 1) * 16);

    float acc[4][8][4];
#pragma unroll
    for (int i = 0; i < 4; i++)
#pragma unroll
        for (int j = 0; j < 8; j++)
#pragma unroll
            for (int q = 0; q < 4; q++) acc[i][j][q] = 0.f;

    // cp.async prefetch of one BK=32 stage (A + B: 16384 B), 128 threads
    auto prefetch = [&](int stage, int kt) {
        const uint32_t so = sb + (uint32_t)stage * STAGE_BY;
        const int k0 = kt * 32;
#pragma unroll
        for (int it = 0; it < 8; it++) {
            int gi = tid + it * 128;
            int tile = gi >> 9;
            int w = gi & 511;
            int row = w >> 2, c = w & 3;
            const char* src = (const char*)(gsrc[tile] + (size_t)row * GK + k0 + c * 8);
            uint32_t dst = so + (uint32_t)(tile * TILE_BY + row * (PADK * 2) + c * 16);
            asm volatile("cp.async.cg.shared.global [%0], [%1], 16;"
                         :: "r"(dst), "l"(src));
        }
        asm volatile("cp.async.commit_group;");
    };

    prefetch(0, 0);
    prefetch(1, 1);
    asm volatile("cp.async.wait_group 1;");
    __syncthreads();

    int st = 0, pst = 2;
    for (int kt = 0; kt < KT_N; kt++) {
        if (kt + 2 < KT_N) prefetch(pst, kt + 2);

        const uint32_t so = sb + (uint32_t)st * STAGE_BY;
#pragma unroll
        for (int ks = 0; ks < 2; ks++) {
            const uint32_t ko = (uint32_t)(ks * 32);
            uint32_t Af[4][4], Bf[4][4];
#pragma unroll
            for (int fm = 0; fm < 4; fm++)
                ldsm4(so + a_off[fm] + ko, Af[fm]);
#pragma unroll
            for (int nf = 0; nf < 4; nf++)
                ldsm4(so + TILE_BY + b_off[nf] + ko, Bf[nf]);
#pragma unroll
            for (int fm = 0; fm < 4; fm++)
#pragma unroll
                for (int fn = 0; fn < 8; fn++) {
                    const int n2 = fn >> 1, j = (fn & 1) * 2;
                    mma_fp16(acc[fm][fn], Af[fm], Bf[n2][j], Bf[n2][j + 1]);
                }
        }

        if (kt + 1 < KT_N) {
            if (kt + 2 < KT_N) {
                asm volatile("cp.async.wait_group 1;");
            } else {
                asm volatile("cp.async.wait_group 0;");
            }
            __syncthreads();
        }
        st = (st == 2) ? 0 : st + 1;
        pst = (pst == 2) ? 0 : pst + 1;
    }

    // epilogue: direct fp32 stores (float2 per fragment row)
    const int mrow = m0 + warp_m * 64 + (lane >> 2);
    const int ncol = n0 + warp_n * 64 + (lane & 3) * 2;
#pragma unroll
    for (int fm = 0; fm < 4; fm++)
#pragma unroll
        for (int fn = 0; fn < 8; fn++) {
            float* p0 = C + (size_t)(mrow + fm * 16) * N + ncol + fn * 8;
            float* p1 = p0 + (size_t)8 * N;
            float2 v0 = {acc[fm][fn][0], acc[fm][fn][1]};
            float2 v1 = {acc[fm][fn][2], acc[fm][fn][3]};
            if (CLIP) {
                v0.x = fminf(fmaxf(v0.x, -CLIP_V), CLIP_V);
                v0.y = fminf(fmaxf(v0.y, -CLIP_V), CLIP_V);
                v1.x = fminf(fmaxf(v1.x, -CLIP_V), CLIP_V);
                v1.y = fminf(fmaxf(v1.y, -CLIP_V), CLIP_V);
            }
            *(float2*)p0 = v0;
            *(float2*)p1 = v1;
        }
}

// ===================================================================
// RoPE + fp16 cast: qkv fp32 -> q16 [T][4096], k16/v16 [T][1024]
// ===================================================================
#define ROPE_TOTAL1 (T_TOK * 40 * 64)
#define ROPE_TOTAL2 (T_TOK * 1024)

__global__ void rope_cast(const float* __restrict__ qkv,
                          const float* __restrict__ cosp,
                          const float* __restrict__ sinp,
                          __half* __restrict__ q16,
                          __half* __restrict__ k16,
                          __half* __restrict__ v16) {
    int idx = blockIdx.x * blockDim.x + threadIdx.x;
    if (idx < ROPE_TOTAL1) {
        int d  = idx & 63;
        int rr = idx >> 6;
        int hh = rr % 40;
        int t  = rr / 40;
        size_t base = (size_t)t * QKV_OUT + (hh < 32 ? hh * 128 : 4096 + (hh - 32) * 128);
        float x1 = qkv[base + d];
        float x2 = qkv[base + 64 + d];
        float c = cosp[t * 64 + d];
        float s = sinp[t * 64 + d];
        float o1 = x1 * c - x2 * s;
        float o2 = x2 * c + x1 * s;
        if (hh < 32) {
            size_t ob = (size_t)t * 4096 + hh * 128;
            q16[ob + d]      = __float2half_rn(o1);
            q16[ob + 64 + d] = __float2half_rn(o2);
        } else {
            size_t ob = (size_t)t * 1024 + (hh - 32) * 128;
            k16[ob + d]      = __float2half_rn(o1);
            k16[ob + 64 + d] = __float2half_rn(o2);
        }
    } else if (idx < ROPE_TOTAL1 + ROPE_TOTAL2) {
        int j = idx - ROPE_TOTAL1;
        int t = j >> 10, d = j & 1023;
        v16[j] = __float2half_rn(qkv[(size_t)t * QKV_OUT + 5120 + d]);
    }
}

// ===================================================================
// Flash attention, fp16 mma.sync, varlen causal, GQA (R13-proven).
// ===================================================================
#define APAD 136
#define ATTN_SMEM (3 * 64 * APAD * 2)   // Qs, Ks, Vs = 52224 B

__global__ __launch_bounds__(128) void attn_mma(
    const __half* __restrict__ Q, const __half* __restrict__ K,
    const __half* __restrict__ V, const int* __restrict__ cu,
    __half* __restrict__ att16) {
    extern __shared__ __half hsm[];
    __half* Qs = hsm;
    __half* Ks = Qs + 64 * APAD;
    __half* Vs = Ks + 64 * APAD;

    const int tid = threadIdx.x, w = tid >> 5, lane = tid & 31;
    const int g = lane >> 3, r = lane & 7;
    const int qt = blockIdx.x, h = blockIdx.y;
    const int q0 = qt * 64, kh = h >> 2;

    int seg_start = 0;
#pragma unroll
    for (int s = 1; s < 4; s++) {
        int c = cu[s];
        if (q0 >= c) seg_start = c;
    }

    // load Q tile (64 x 128 fp16)
#pragma unroll
    for (int it = 0; it < 8; it++) {
        int gi = tid + it * 128;
        int row = gi >> 4, c = gi & 15;
        *(uint4*)&Qs[row * APAD + c * 8] =
            *(const uint4*)&Q[(size_t)(q0 + row) * 4096 + h * 128 + c * 8];
    }

    const uint32_t q_off = smem_u32(Qs)
        + (uint32_t)(((w * 16 + (g & 1) * 8 + r) * APAD + (g >> 1) * 8) * 2);
    const uint32_t k_off = smem_u32(Ks)
        + (uint32_t)((((g >> 1) * 8 + r) * APAD + (g & 1) * 8) * 2);
    const uint32_t v_off = smem_u32(Vs)
        + (uint32_t)((((g & 1) * 8 + r) * APAD + (g >> 1) * 8) * 2);

    float Oa[16][4];
#pragma unroll
    for (int i = 0; i < 16; i++)
#pragma unroll
        for (int j = 0; j < 4; j++) Oa[i][j] = 0.f;
    float m0 = -1e30f, m1 = -1e30f, l0 = 0.f, l1 = 0.f;
    const int row0 = q0 + w * 16 + (lane >> 2), row1 = row0 + 8;
    const float sc = 0.08838834764831845f * 1.4426950408889634f;  // scale*log2e

    for (int kstart = seg_start; kstart < q0 + 64; kstart += 64) {
        __syncthreads();
#pragma unroll
        for (int it = 0; it < 8; it++) {
            int gi = tid + it * 128;
            int row = gi >> 4, c = gi & 15;
            size_t gb = (size_t)(kstart + row) * 1024 + kh * 128 + c * 8;
            *(uint4*)&Ks[row * APAD + c * 8] = *(const uint4*)&K[gb];
            *(uint4*)&Vs[row * APAD + c * 8] = *(const uint4*)&V[gb];
        }
        __syncthreads();

        // ---- S = Q K^T ----
        float Sa[8][4];
#pragma unroll
        for (int i = 0; i < 8; i++)
#pragma unroll
            for (int j = 0; j < 4; j++) Sa[i][j] = 0.f;
#pragma unroll
        for (int kstep = 0; kstep < 8; kstep++) {
            uint32_t qf[4];
            ldsm4(q_off + kstep * 32, qf);
#pragma unroll
            for (int nb16 = 0; nb16 < 4; nb16++) {
                uint32_t kf[4];
                ldsm4(k_off + nb16 * (16 * APAD * 2) + kstep * 32, kf);
                mma_fp16(Sa[2 * nb16], qf, kf[0], kf[1]);
                mma_fp16(Sa[2 * nb16 + 1], qf, kf[2], kf[3]);
            }
        }

        // scale to log2 domain + causal mask (only last tile)
#pragma unroll
        for (int nb = 0; nb < 8; nb++)
#pragma unroll
            for (int e = 0; e < 4; e++) Sa[nb][e] *= sc;
        if (kstart == q0) {
#pragma unroll
            for (int nb = 0; nb < 8; nb++) {
                int cg = kstart + nb * 8 + 2 * (lane & 3);
                if (cg > row0)     Sa[nb][0] = -1e30f;
                if (cg + 1 > row0) Sa[nb][1] = -1e30f;
                if (cg > row1)     Sa[nb][2] = -1e30f;
                if (cg + 1 > row1) Sa[nb][3] = -1e30f;
            }
        }

        // ---- online softmax ----
        float mx0 = -1e30f, mx1 = -1e30f;
#pragma unroll
        for (int nb = 0; nb < 8; nb++) {
            mx0 = fmaxf(mx0, fmaxf(Sa[nb][0], Sa[nb][1]));
            mx1 = fmaxf(mx1, fmaxf(Sa[nb][2], Sa[nb][3]));
        }
        mx0 = fmaxf(mx0, __shfl_xor_sync(0xffffffffu, mx0, 1));
        mx0 = fmaxf(mx0, __shfl_xor_sync(0xffffffffu, mx0, 2));
        mx1 = fmaxf(mx1, __shfl_xor_sync(0xffffffffu, mx1, 1));
        mx1 = fmaxf(mx1, __shfl_xor_sync(0xffffffffu, mx1, 2));
        float mn0 = fmaxf(m0, mx0), mn1 = fmaxf(m1, mx1);
        float c0 = exp2f(m0 - mn0), c1 = exp2f(m1 - mn1);
        m0 = mn0;
        m1 = mn1;
        float s0 = 0.f, s1 = 0.f;
        uint32_t pA[8], pB[8];
#pragma unroll
        for (int nb = 0; nb < 8; nb++) {
            float p0 = exp2f(Sa[nb][0] - mn0);
            float p1 = exp2f(Sa[nb][1] - mn0);
            float p2 = exp2f(Sa[nb][2] - mn1);
            float p3 = exp2f(Sa[nb][3] - mn1);
            s0 += p0 + p1;
            s1 += p2 + p3;
            pA[nb] = pack_half2(p0, p1);
            pB[nb] = pack_half2(p2, p3);
        }
        s0 += __shfl_xor_sync(0xffffffffu, s0, 1);
        s0 += __shfl_xor_sync(0xffffffffu, s0, 2);
        s1 += __shfl_xor_sync(0xffffffffu, s1, 1);
        s1 += __shfl_xor_sync(0xffffffffu, s1, 2);
        l0 = l0 * c0 + s0;
        l1 = l1 * c1 + s1;
#pragma unroll
        for (int db = 0; db < 16; db++) {
            Oa[db][0] *= c0;
            Oa[db][1] *= c0;
            Oa[db][2] *= c1;
            Oa[db][3] *= c1;
        }

        // ---- O += P V ----
#pragma unroll
        for (int ks2 = 0; ks2 < 4; ks2++) {
            uint32_t af[4] = {pA[2 * ks2], pB[2 * ks2],
                              pA[2 * ks2 + 1], pB[2 * ks2 + 1]};
#pragma unroll
            for (int db16 = 0; db16 < 8; db16++) {
                uint32_t vf[4];
                ldsm4t(v_off + ks2 * (16 * APAD * 2) + db16 * 32, vf);
                mma_fp16(Oa[2 * db16], af, vf[0], vf[1]);
                mma_fp16(Oa[2 * db16 + 1], af, vf[2], vf[3]);
            }
        }
    }

    // epilogue: normalize, write fp16 directly
    float i0 = 1.f / l0, i1 = 1.f / l1;
#pragma unroll
    for (int db = 0; db < 16; db++) {
        int col = h * 128 + db * 8 + (lane & 3) * 2;
        float x0 = Oa[db][0] * i0, x1 = Oa[db][1] * i0;
        float x2 = Oa[db][2] * i1, x3 = Oa[db][3] * i1;
        *(uint32_t*)&att16[(size_t)row0 * 4096 + col] = pack_half2(x0, x1);
        *(uint32_t*)&att16[(size_t)row1 * 4096 + col] = pack_half2(x2, x3);
    }
}

// ===================================================================
// launch
// ===================================================================
extern "C" void kernel_launch(void* const* d_in, const int* in_sizes, int n_in,
                              void* d_out, int out_size) {
    const float* hidden = (const float*)d_in[0];
    const float* w_qkv  = (const float*)d_in[1];
    const float* w_o    = (const float*)d_in[2];
    const float* cosp   = (const float*)d_in[3];
    const float* sinp   = (const float*)d_in[4];
    const int*   cu     = (const int*)d_in[5];
    float* out = (float*)d_out;

    float* qkvp;
    __half *h16, *wq16, *wo16, *at16, *q16, *k16, *v16;
    cudaGetSymbolAddress((void**)&qkvp, g_qkv);
    cudaGetSymbolAddress((void**)&h16,  g_hid16);
    cudaGetSymbolAddress((void**)&wq16, g_wqkv16);
    cudaGetSymbolAddress((void**)&wo16, g_wo16);
    cudaGetSymbolAddress((void**)&at16, g_att16);
    cudaGetSymbolAddress((void**)&q16,  g_q16);
    cudaGetSymbolAddress((void**)&k16,  g_k16);
    cudaGetSymbolAddress((void**)&v16,  g_v16);

    cudaFuncSetAttribute(gemm_mma_fp16<true>,
                         cudaFuncAttributeMaxDynamicSharedMemorySize, GEMM_SMEM);
    cudaFuncSetAttribute(gemm_mma_fp16<false>,
                         cudaFuncAttributeMaxDynamicSharedMemorySize, GEMM_SMEM);
    cudaFuncSetAttribute(attn_mma,
                         cudaFuncAttributeMaxDynamicSharedMemorySize, ATTN_SMEM);

    // 0) cast inputs/weights to fp16
    {
        int n4;
        n4 = T_TOK * D_MODEL / 4;
        cast_fp16<<<(n4 + 255) / 256, 256>>>(hidden, h16, n4);
        n4 = QKV_OUT * D_MODEL / 4;
        cast_fp16<<<(n4 + 255) / 256, 256>>>(w_qkv, wq16, n4);
        n4 = D_MODEL * D_MODEL / 4;
        cast_fp16<<<(n4 + 255) / 256, 256>>>(w_o, wo16, n4);
    }
    // 1) QKV projection + clip (fp16, warp tile 64x64, 3-stage)
    gemm_mma_fp16<true><<<dim3(QKV_OUT / 128, T_TOK / 128), 128, GEMM_SMEM>>>(
        h16, wq16, qkvp, QKV_OUT);
    // 2) RoPE + fp16 cast
    {
        int total = ROPE_TOTAL1 + ROPE_TOTAL2;
        rope_cast<<<(total + 255) / 256, 256>>>(qkvp, cosp, sinp, q16, k16, v16);
    }
    // 3) attention (fp16 tensor cores) -> fp16 directly
    attn_mma<<<dim3(T_TOK / 64, N_HEADS), 128, ATTN_SMEM>>>(q16, k16, v16, cu, at16);
    // 4) output projection (fp16, warp tile 64x64, 3-stage)
    gemm_mma_fp16<false><<<dim3(D_MODEL / 128, T_TOK / 128), 128, GEMM_SMEM>>>(
        at16, wo16, out, D_MODEL);
}